// round 2
// baseline (speedup 1.0000x reference)
#include <cuda_runtime.h>
#include <math.h>

#define HEADS 8
#define HEAD_DIM 32
#define CH 256
#define INNER 256
#define LL 2304
#define BB 4
#define TABLE_W 127     // 2*MAX_RES-1
#define BR 95           // 2*48-1
#define EPS 1e-6f

// ---------------- scratch (device globals: no allocation allowed) ----------
__device__ float g_xn[BB*LL*CH];
__device__ float g_cn[BB*LL*CH];
__device__ float g_q [BB*LL*INNER];
__device__ float g_k [BB*LL*INNER];
__device__ float g_v [BB*LL*INNER];
__device__ float g_o [BB*LL*INNER];
__device__ float g_biasc[HEADS*BR*BR];

// ---------------- packed f32x2 helpers (sm_100+) ---------------------------
__device__ __forceinline__ unsigned long long ffma2(unsigned long long a,
                                                    unsigned long long b,
                                                    unsigned long long c) {
    unsigned long long d;
    asm("fma.rn.f32x2 %0, %1, %2, %3;" : "=l"(d) : "l"(a), "l"(b), "l"(c));
    return d;
}
__device__ __forceinline__ unsigned long long fmul2(unsigned long long a,
                                                    unsigned long long b) {
    unsigned long long d;
    asm("mul.rn.f32x2 %0, %1, %2;" : "=l"(d) : "l"(a), "l"(b));
    return d;
}
__device__ __forceinline__ unsigned long long pack2(float x, float y) {
    unsigned long long d;
    asm("mov.b64 %0, {%1, %2};" : "=l"(d) : "f"(x), "f"(y));
    return d;
}
__device__ __forceinline__ float2 unpack2(unsigned long long a) {
    float2 r;
    asm("mov.b64 {%0, %1}, %2;" : "=f"(r.x), "=f"(r.y) : "l"(a));
    return r;
}

// ---------------- LayerNorm over C of NCHW -> [B, L, C] row-major ----------
// DST 0 -> g_xn, DST 1 -> g_cn.  grid: (LL/32, BB), block: 256
template<int DST>
__global__ void ln_kernel(const float* __restrict__ in,
                          const float* __restrict__ w,
                          const float* __restrict__ bvec)
{
    __shared__ float s[CH*33];          // s[c*33 + p], 32 pixels per block
    __shared__ float rsum[8][32];
    __shared__ float rsq[8][32];
    __shared__ float mu_s[32];
    __shared__ float rs_s[32];

    float* out = (DST == 0) ? g_xn : g_cn;

    int tx = threadIdx.x & 31;          // pixel within block
    int ty = threadIdx.x >> 5;          // channel group lane
    int b  = blockIdx.y;
    int l0 = blockIdx.x * 32;

    const float* inb = in + (size_t)b*CH*LL + l0;
    float sm = 0.f, sq = 0.f;
    #pragma unroll 4
    for (int cg = 0; cg < 32; ++cg) {
        int c = cg*8 + ty;
        float vv = inb[(size_t)c*LL + tx];   // coalesced over tx
        s[c*33 + tx] = vv;
        sm += vv; sq += vv*vv;
    }
    rsum[ty][tx] = sm; rsq[ty][tx] = sq;
    __syncthreads();
    if (threadIdx.x < 32) {
        float a = 0.f, c2 = 0.f;
        #pragma unroll
        for (int j = 0; j < 8; ++j) { a += rsum[j][threadIdx.x]; c2 += rsq[j][threadIdx.x]; }
        float mu  = a * (1.f/CH);
        float var = c2 * (1.f/CH) - mu*mu;   // biased variance
        mu_s[threadIdx.x] = mu;
        rs_s[threadIdx.x] = rsqrtf(var + EPS);
    }
    __syncthreads();
    float* ob = out + ((size_t)b*LL + l0)*CH;
    #pragma unroll 4
    for (int i = threadIdx.x; i < 32*CH; i += 256) {
        int p = i >> 8, c = i & 255;
        float vv = s[c*33 + p];
        ob[(size_t)p*CH + c] = (vv - mu_s[p]) * rs_s[p] * w[c] + bvec[c];   // coalesced
    }
}

// ---------------- compact rel bias: biasc[h][dh+47][dw+47] -----------------
__global__ void bias_compact(const float* __restrict__ rel_table)
{
    int i = blockIdx.x*256 + threadIdx.x;
    if (i >= HEADS*BR*BR) return;
    int h  = i / (BR*BR);
    int rr = i - h*(BR*BR);
    int dh = rr / BR;        // dh+47
    int dw = rr - dh*BR;     // dw+47
    int idx = (dh + 16)*TABLE_W + (dw + 16);   // (dh-47+63)*127 + (dw-47+63)
    g_biasc[i] = rel_table[idx*HEADS + h];
}

// ---------------- SGEMM: C[M,256] = A[M,256] * W[256,256]^T + bias ---------
// MODE 0: A=g_xn -> C=g_q    MODE 1: A=g_cn -> C=g_k    MODE 2: A=g_cn -> C=g_v
// MODE 3: A=g_o, C=Cout (NCHW residual write, +resid)
// BM=BN=64, BK=16, 256 threads, 4x4 microtile via f32x2 (8 FFMA2/k-step)
template<int MODE>
__global__ __launch_bounds__(256) void gemm256(const float* __restrict__ W,
                        const float* __restrict__ bias,
                        float* __restrict__ Cout,
                        const float* __restrict__ resid)
{
    __shared__ float As[16][68];
    __shared__ float Ws[16][68];

    const float* A = (MODE == 0) ? g_xn : (MODE == 3) ? g_o : g_cn;
    float* C = (MODE == 0) ? g_q : (MODE == 1) ? g_k : (MODE == 2) ? g_v : Cout;

    int tid = threadIdx.x;
    int tn = tid & 15, tm = tid >> 4;
    int m0 = blockIdx.x * 64, n0 = blockIdx.y * 64;

    int lrow = tid >> 2;          // 0..63
    int lk4  = (tid & 3) * 4;     // 0,4,8,12
    const float* Ap  = A + (size_t)(m0 + lrow)*256 + lk4;
    const float* Wpp = W + (size_t)(n0 + lrow)*256 + lk4;

    unsigned long long acc2[4][2];
    #pragma unroll
    for (int i = 0; i < 4; ++i) { acc2[i][0] = 0ull; acc2[i][1] = 0ull; }

    for (int k0 = 0; k0 < 256; k0 += 16) {
        float4 a4 = *(const float4*)(Ap + k0);
        float4 w4 = *(const float4*)(Wpp + k0);
        __syncthreads();
        As[lk4+0][lrow] = a4.x; As[lk4+1][lrow] = a4.y;
        As[lk4+2][lrow] = a4.z; As[lk4+3][lrow] = a4.w;
        Ws[lk4+0][lrow] = w4.x; Ws[lk4+1][lrow] = w4.y;
        Ws[lk4+2][lrow] = w4.z; Ws[lk4+3][lrow] = w4.w;
        __syncthreads();
        #pragma unroll
        for (int k = 0; k < 16; ++k) {
            float4 av = *(const float4*)&As[k][tm*4];          // rows 272B -> 16B aligned
            ulonglong2 w2 = *(const ulonglong2*)&Ws[k][tn*4];
            unsigned long long a0 = pack2(av.x, av.x);
            unsigned long long a1 = pack2(av.y, av.y);
            unsigned long long a2 = pack2(av.z, av.z);
            unsigned long long a3 = pack2(av.w, av.w);
            acc2[0][0] = ffma2(a0, w2.x, acc2[0][0]);
            acc2[0][1] = ffma2(a0, w2.y, acc2[0][1]);
            acc2[1][0] = ffma2(a1, w2.x, acc2[1][0]);
            acc2[1][1] = ffma2(a1, w2.y, acc2[1][1]);
            acc2[2][0] = ffma2(a2, w2.x, acc2[2][0]);
            acc2[2][1] = ffma2(a2, w2.y, acc2[2][1]);
            acc2[3][0] = ffma2(a3, w2.x, acc2[3][0]);
            acc2[3][1] = ffma2(a3, w2.y, acc2[3][1]);
        }
    }

    float acc[4][4];
    #pragma unroll
    for (int i = 0; i < 4; ++i) {
        float2 p0 = unpack2(acc2[i][0]), p1 = unpack2(acc2[i][1]);
        acc[i][0] = p0.x; acc[i][1] = p0.y; acc[i][2] = p1.x; acc[i][3] = p1.y;
    }

    if (MODE != 3) {
        float4 bb = *(const float4*)(bias + n0 + tn*4);
        #pragma unroll
        for (int i = 0; i < 4; ++i) {
            float4 r;
            r.x = acc[i][0] + bb.x; r.y = acc[i][1] + bb.y;
            r.z = acc[i][2] + bb.z; r.w = acc[i][3] + bb.w;
            *(float4*)(C + (size_t)(m0 + tm*4 + i)*256 + n0 + tn*4) = r;
        }
    } else {
        int b = m0 / LL;                         // 64-row tiles never straddle batches
        int l = (m0 - b*LL) + tm*4;
        #pragma unroll
        for (int j = 0; j < 4; ++j) {
            int n = n0 + tn*4 + j;
            size_t ad = ((size_t)b*256 + n)*LL + l;
            float4 xv = *(const float4*)(resid + ad);
            float bj = bias[n];
            float4 r;
            r.x = xv.x + acc[0][j] + bj;
            r.y = xv.y + acc[1][j] + bj;
            r.z = xv.z + acc[2][j] + bj;
            r.w = xv.w + acc[3][j] + bj;
            *(float4*)(C + ad) = r;
        }
    }
}

// ---------------- attention: per (b,h), 128 query rows per block ----------
// grid (LL/128, BB*HEADS), block 128. One thread = one query row.
__global__ __launch_bounds__(128) void attn_kernel()
{
    __shared__ float  biasS[52*BR];     // bias sub-table for this block's qh range
    __shared__ float4 Ks[64*8];         // 64 keys x 32 floats
    __shared__ float4 Vs[64*8];

    int tid = threadIdx.x;
    int bh = blockIdx.y;
    int b = bh >> 3, h = bh & 7;
    int l0 = blockIdx.x * 128;

    int qh_min = l0 / 48;
    int qh_max = (l0 + 127) / 48;
    int rows = qh_max - qh_min + 48;    // <= 51

    const float* bc = g_biasc + h*BR*BR + qh_min*BR;
    for (int i = tid; i < rows*BR; i += 128) biasS[i] = bc[i];

    int l  = l0 + tid;
    int qh = l / 48, qw = l - qh*48;
    int qBase = (qh - qh_min + 47)*BR + qw + 47;   // bias idx = qBase - kh*95 - kw

    const ulonglong2* qp = (const ulonglong2*)(g_q + ((size_t)b*LL + l)*256 + h*32);
    unsigned long long q2[16];
    #pragma unroll
    for (int j = 0; j < 8; ++j) { ulonglong2 t = qp[j]; q2[2*j] = t.x; q2[2*j+1] = t.y; }

    unsigned long long o2[16];
    #pragma unroll
    for (int j = 0; j < 16; ++j) o2[j] = 0ull;
    float m = -1e30f, lsum = 0.f;
    const float scale = 0.17677669529663687f;   // 1/sqrt(32)

    const float4* kg = (const float4*)(g_k + (size_t)b*LL*256 + h*32);
    const float4* vg = (const float4*)(g_v + (size_t)b*LL*256 + h*32);

    for (int kt = 0; kt < LL; kt += 64) {
        __syncthreads();
        #pragma unroll
        for (int i = 0; i < 4; ++i) {
            int idx = tid + i*128;              // 0..511
            int row = idx >> 3, col = idx & 7;
            Ks[idx] = kg[(size_t)(kt + row)*64 + col];
            Vs[idx] = vg[(size_t)(kt + row)*64 + col];
        }
        __syncthreads();

        int kh = kt / 48, kw = kt - (kt/48)*48;
        int bidx = qBase - kh*BR - kw;

        for (int k = 0; k < 64; ++k) {
            float bval = biasS[bidx];           // prefetch bias (broadcast-free LDS)
            if (++kw == 48) { kw = 0; bidx -= 48; } else { --bidx; }

            const ulonglong2* kp = (const ulonglong2*)&Ks[k*8];
            unsigned long long a0 = 0ull, a1 = 0ull;
            #pragma unroll
            for (int j = 0; j < 4; ++j) {
                ulonglong2 t0 = kp[2*j], t1 = kp[2*j+1];
                a0 = ffma2(q2[4*j+0], t0.x, a0);
                a1 = ffma2(q2[4*j+1], t0.y, a1);
                a0 = ffma2(q2[4*j+2], t1.x, a0);
                a1 = ffma2(q2[4*j+3], t1.y, a1);
            }
            float2 f0 = unpack2(a0), f1 = unpack2(a1);
            float s = (f0.x + f0.y) + (f1.x + f1.y);
            s = s * scale + bval;

            if (s > m) {                        // rare after first few keys
                float cfac = __expf(m - s);
                m = s;
                lsum *= cfac;
                unsigned long long c2 = pack2(cfac, cfac);
                #pragma unroll
                for (int j = 0; j < 16; ++j) o2[j] = fmul2(o2[j], c2);
            }
            float p = __expf(s - m);
            lsum += p;
            unsigned long long p2 = pack2(p, p);
            const ulonglong2* vp = (const ulonglong2*)&Vs[k*8];
            #pragma unroll
            for (int j = 0; j < 8; ++j) {
                ulonglong2 t = vp[j];
                o2[2*j]   = ffma2(p2, t.x, o2[2*j]);
                o2[2*j+1] = ffma2(p2, t.y, o2[2*j+1]);
            }
        }
    }

    float rdiv = 1.f / lsum;
    float4* og = (float4*)(g_o + ((size_t)b*LL + l)*256 + h*32);
    #pragma unroll
    for (int j = 0; j < 8; ++j) {
        float2 x0 = unpack2(o2[2*j]), x1 = unpack2(o2[2*j+1]);
        og[j] = make_float4(x0.x*rdiv, x0.y*rdiv, x1.x*rdiv, x1.y*rdiv);
    }
}

// ---------------------------------------------------------------------------
extern "C" void kernel_launch(void* const* d_in, const int* in_sizes, int n_in,
                              void* d_out, int out_size)
{
    const float* x      = (const float*)d_in[0];
    const float* ctx    = (const float*)d_in[1];
    const float* ln_x_w = (const float*)d_in[2];
    const float* ln_x_b = (const float*)d_in[3];
    const float* ln_c_w = (const float*)d_in[4];
    const float* ln_c_b = (const float*)d_in[5];
    const float* Wq     = (const float*)d_in[6];
    const float* bq     = (const float*)d_in[7];
    const float* Wk     = (const float*)d_in[8];
    const float* bk     = (const float*)d_in[9];
    const float* Wv     = (const float*)d_in[10];
    const float* bv     = (const float*)d_in[11];
    const float* Wp     = (const float*)d_in[12];
    const float* bp     = (const float*)d_in[13];
    const float* rel    = (const float*)d_in[14];
    float* out = (float*)d_out;

    dim3 lngrid(LL/32, BB);
    ln_kernel<0><<<lngrid, 256>>>(x,   ln_x_w, ln_x_b);
    ln_kernel<1><<<lngrid, 256>>>(ctx, ln_c_w, ln_c_b);
    bias_compact<<<(HEADS*BR*BR + 255)/256, 256>>>(rel);

    dim3 ggrid(BB*LL/64, INNER/64);
    gemm256<0><<<ggrid, 256>>>(Wq, bq, nullptr, nullptr);
    gemm256<1><<<ggrid, 256>>>(Wk, bk, nullptr, nullptr);
    gemm256<2><<<ggrid, 256>>>(Wv, bv, nullptr, nullptr);

    attn_kernel<<<dim3(LL/128, BB*HEADS), 128>>>();

    gemm256<3><<<ggrid, 256>>>(Wp, bp, out, x);
}

// round 5
// speedup vs baseline: 3.2291x; 3.2291x over previous
#include <cuda_runtime.h>
#include <cuda_bf16.h>
#include <math.h>
#include <cstdint>

#define HEADS 8
#define HEAD_DIM 32
#define CH 256
#define INNER 256
#define LL 2304
#define BB 4
#define TABLE_W 127     // 2*MAX_RES-1
#define BR 95           // 2*48-1
#define EPS 1e-6f
#define LOG2E 1.4426950408889634f
#define SC 0.25503486f  // (1/sqrt(32)) * log2(e)  -- folded into Q

// ---------------- scratch (device globals: no allocation allowed) ----------
__device__ float g_xn[BB*LL*CH];
__device__ float g_cn[BB*LL*CH];
__device__ float g_o [BB*LL*INNER];
__device__ float g_biasc[HEADS*BR*BR];                      // pre-scaled by log2e
__device__ __align__(128) __nv_bfloat16 g_qb[BB*HEADS*LL*32];   // Q (pre-scaled by SC)
__device__ __align__(128) __nv_bfloat16 g_kb[BB*HEADS*LL*32];
__device__ __align__(128) __nv_bfloat16 g_vt[BB*HEADS*32*LL];   // V transposed [bh][d][l]

// ---------------- f32x2 helpers (GEMM inner loop) --------------------------
__device__ __forceinline__ unsigned long long ffma2(unsigned long long a,
                                                    unsigned long long b,
                                                    unsigned long long c) {
    unsigned long long d;
    asm("fma.rn.f32x2 %0, %1, %2, %3;" : "=l"(d) : "l"(a), "l"(b), "l"(c));
    return d;
}
__device__ __forceinline__ unsigned long long pack2(float x, float y) {
    unsigned long long d;
    asm("mov.b64 %0, {%1, %2};" : "=l"(d) : "f"(x), "f"(y));
    return d;
}
__device__ __forceinline__ float2 unpack2(unsigned long long a) {
    float2 r;
    asm("mov.b64 {%0, %1}, %2;" : "=f"(r.x), "=f"(r.y) : "l"(a));
    return r;
}
__device__ __forceinline__ float ex2f(float x) {
    float r;
    asm("ex2.approx.f32 %0, %1;" : "=f"(r) : "f"(x));
    return r;
}

// ---------------- HMMA m16n8k16 bf16 (sm_80+, legal at compute_103) --------
__device__ __forceinline__ void mma16816(float* c, const uint32_t* a, const uint32_t* b) {
    asm volatile(
        "mma.sync.aligned.m16n8k16.row.col.f32.bf16.bf16.f32 "
        "{%0,%1,%2,%3}, {%4,%5,%6,%7}, {%8,%9}, {%0,%1,%2,%3};"
        : "+f"(c[0]), "+f"(c[1]), "+f"(c[2]), "+f"(c[3])
        : "r"(a[0]), "r"(a[1]), "r"(a[2]), "r"(a[3]), "r"(b[0]), "r"(b[1]));
}

// ---------------- LayerNorm over C of NCHW -> [B, L, C] row-major ----------
template<int DST>
__global__ void ln_kernel(const float* __restrict__ in,
                          const float* __restrict__ w,
                          const float* __restrict__ bvec)
{
    __shared__ float s[CH*33];
    __shared__ float rsum[8][32];
    __shared__ float rsq[8][32];
    __shared__ float mu_s[32];
    __shared__ float rs_s[32];

    float* out = (DST == 0) ? g_xn : g_cn;

    int tx = threadIdx.x & 31;
    int ty = threadIdx.x >> 5;
    int b  = blockIdx.y;
    int l0 = blockIdx.x * 32;

    const float* inb = in + (size_t)b*CH*LL + l0;
    float sm = 0.f, sq = 0.f;
    #pragma unroll 4
    for (int cg = 0; cg < 32; ++cg) {
        int c = cg*8 + ty;
        float vv = inb[(size_t)c*LL + tx];
        s[c*33 + tx] = vv;
        sm += vv; sq += vv*vv;
    }
    rsum[ty][tx] = sm; rsq[ty][tx] = sq;
    __syncthreads();
    if (threadIdx.x < 32) {
        float a = 0.f, c2 = 0.f;
        #pragma unroll
        for (int j = 0; j < 8; ++j) { a += rsum[j][threadIdx.x]; c2 += rsq[j][threadIdx.x]; }
        float mu  = a * (1.f/CH);
        float var = c2 * (1.f/CH) - mu*mu;
        mu_s[threadIdx.x] = mu;
        rs_s[threadIdx.x] = rsqrtf(var + EPS);
    }
    __syncthreads();
    float* ob = out + ((size_t)b*LL + l0)*CH;
    #pragma unroll 4
    for (int i = threadIdx.x; i < 32*CH; i += 256) {
        int p = i >> 8, c = i & 255;
        float vv = s[c*33 + p];
        ob[(size_t)p*CH + c] = (vv - mu_s[p]) * rs_s[p] * w[c] + bvec[c];
    }
}

// ---------------- compact rel bias (pre-scaled by log2e) -------------------
__global__ void bias_compact(const float* __restrict__ rel_table)
{
    int i = blockIdx.x*256 + threadIdx.x;
    if (i >= HEADS*BR*BR) return;
    int h  = i / (BR*BR);
    int rr = i - h*(BR*BR);
    int dh = rr / BR;
    int dw = rr - dh*BR;
    int idx = (dh + 16)*TABLE_W + (dw + 16);
    g_biasc[i] = rel_table[idx*HEADS + h] * LOG2E;
}

// ---------------- SGEMM: C[M,256] = A[M,256] * W[256,256]^T + bias ---------
// MODE 0: g_xn -> g_qb (bf16 [bh][l][32], scaled by SC)
// MODE 1: g_cn -> g_kb (bf16 [bh][l][32])
// MODE 2: g_cn -> g_vt (bf16 transposed [bh][d][l])
// MODE 3: g_o  -> Cout (NCHW residual write, f32)
template<int MODE>
__global__ __launch_bounds__(256) void gemm256(const float* __restrict__ W,
                        const float* __restrict__ bias,
                        float* __restrict__ Cout,
                        const float* __restrict__ resid)
{
    __shared__ float As[16][68];
    __shared__ float Ws[16][68];

    const float* A = (MODE == 0) ? g_xn : (MODE == 3) ? g_o : g_cn;

    int tid = threadIdx.x;
    int tn = tid & 15, tm = tid >> 4;
    int m0 = blockIdx.x * 64, n0 = blockIdx.y * 64;

    int lrow = tid >> 2;
    int lk4  = (tid & 3) * 4;
    const float* Ap  = A + (size_t)(m0 + lrow)*256 + lk4;
    const float* Wpp = W + (size_t)(n0 + lrow)*256 + lk4;

    unsigned long long acc2[4][2];
    #pragma unroll
    for (int i = 0; i < 4; ++i) { acc2[i][0] = 0ull; acc2[i][1] = 0ull; }

    for (int k0 = 0; k0 < 256; k0 += 16) {
        float4 a4 = *(const float4*)(Ap + k0);
        float4 w4 = *(const float4*)(Wpp + k0);
        __syncthreads();
        As[lk4+0][lrow] = a4.x; As[lk4+1][lrow] = a4.y;
        As[lk4+2][lrow] = a4.z; As[lk4+3][lrow] = a4.w;
        Ws[lk4+0][lrow] = w4.x; Ws[lk4+1][lrow] = w4.y;
        Ws[lk4+2][lrow] = w4.z; Ws[lk4+3][lrow] = w4.w;
        __syncthreads();
        #pragma unroll
        for (int k = 0; k < 16; ++k) {
            float4 av = *(const float4*)&As[k][tm*4];
            ulonglong2 w2 = *(const ulonglong2*)&Ws[k][tn*4];
            unsigned long long a0 = pack2(av.x, av.x);
            unsigned long long a1 = pack2(av.y, av.y);
            unsigned long long a2 = pack2(av.z, av.z);
            unsigned long long a3 = pack2(av.w, av.w);
            acc2[0][0] = ffma2(a0, w2.x, acc2[0][0]);
            acc2[0][1] = ffma2(a0, w2.y, acc2[0][1]);
            acc2[1][0] = ffma2(a1, w2.x, acc2[1][0]);
            acc2[1][1] = ffma2(a1, w2.y, acc2[1][1]);
            acc2[2][0] = ffma2(a2, w2.x, acc2[2][0]);
            acc2[2][1] = ffma2(a2, w2.y, acc2[2][1]);
            acc2[3][0] = ffma2(a3, w2.x, acc2[3][0]);
            acc2[3][1] = ffma2(a3, w2.y, acc2[3][1]);
        }
    }

    float acc[4][4];
    #pragma unroll
    for (int i = 0; i < 4; ++i) {
        float2 p0 = unpack2(acc2[i][0]), p1 = unpack2(acc2[i][1]);
        acc[i][0] = p0.x; acc[i][1] = p0.y; acc[i][2] = p1.x; acc[i][3] = p1.y;
    }

    int b = m0 / LL;                       // 64-row tiles never straddle batches
    int lbase = (m0 - b*LL) + tm*4;
    int nn = n0 + tn*4;

    if (MODE == 0 || MODE == 1) {
        __nv_bfloat16* dst = (MODE == 0) ? g_qb : g_kb;
        const float scl = (MODE == 0) ? SC : 1.0f;
        int hh = nn >> 5, d0 = nn & 31;    // 4 consecutive d stay within one head
        float4 bb = *(const float4*)(bias + nn);
        #pragma unroll
        for (int i = 0; i < 4; ++i) {
            __nv_bfloat162 x0 = __float22bfloat162_rn(
                make_float2((acc[i][0]+bb.x)*scl, (acc[i][1]+bb.y)*scl));
            __nv_bfloat162 x1 = __float22bfloat162_rn(
                make_float2((acc[i][2]+bb.z)*scl, (acc[i][3]+bb.w)*scl));
            uint2 u;
            u.x = *(uint32_t*)&x0; u.y = *(uint32_t*)&x1;
            *(uint2*)(&dst[((size_t)(b*8 + hh)*LL + lbase + i)*32 + d0]) = u;
        }
    } else if (MODE == 2) {
        int hh = nn >> 5, d0 = nn & 31;
        #pragma unroll
        for (int j = 0; j < 4; ++j) {
            float bj = bias[nn + j];
            #pragma unroll
            for (int i = 0; i < 4; ++i)
                g_vt[((size_t)(b*8 + hh)*32 + d0 + j)*LL + lbase + i] =
                    __float2bfloat16(acc[i][j] + bj);
        }
    } else {
        #pragma unroll
        for (int j = 0; j < 4; ++j) {
            int n = nn + j;
            size_t ad = ((size_t)b*256 + n)*LL + lbase;
            float4 xv = *(const float4*)(resid + ad);
            float bj = bias[n];
            float4 r;
            r.x = xv.x + acc[0][j] + bj;
            r.y = xv.y + acc[1][j] + bj;
            r.z = xv.z + acc[2][j] + bj;
            r.w = xv.w + acc[3][j] + bj;
            *(float4*)(Cout + ad) = r;
        }
    }
}

// ---------------- HMMA flash attention -------------------------------------
// grid (LL/128, BB*HEADS), 256 threads (8 warps). Warp w owns q-rows
// [l0 + w*16, +16) as one m16 tile. Keys iterated in 64-chunks.
__global__ void __launch_bounds__(256) attn_hmma()
{
    __shared__ __align__(16) char KsB[64*80];     // K chunk [key][d] pitch 80B
    __shared__ __align__(16) char VtB[32*144];    // V^T chunk [d][key] pitch 144B
    __shared__ float biasS[52*BR];                // bias sub-table (<=51 rows used)
    __shared__ int   kOffS[LL];                   // kh*95+kw per key

    int tid = threadIdx.x;
    int w = tid >> 5, lane = tid & 31;
    int g = lane >> 2, tg = lane & 3;
    int bh = blockIdx.y;
    int b = bh >> 3, h = bh & 7;
    int l0 = blockIdx.x * 128;

    // key-offset table (whole sequence)
    for (int i = tid; i < LL; i += 256) {
        int kh = i / 48;
        kOffS[i] = kh*BR + (i - kh*48);
    }
    // bias sub-table for this q-tile's qh range
    int qh_min = l0 / 48;
    {
        int qh_max = (l0 + 127) / 48;
        int rows = qh_max - qh_min + 48;          // <= 51
        const float* bc = g_biasc + h*BR*BR + qh_min*BR;
        for (int i = tid; i < rows*BR; i += 256) biasS[i] = bc[i];
    }

    // Q fragments (2 ksteps x 4 regs). Q already scaled by SC.
    int r0 = l0 + w*16 + g;
    int r1 = r0 + 8;
    uint32_t qa[2][4];
    {
        const __nv_bfloat16* q0 = g_qb + ((size_t)bh*LL + r0)*32;
        const __nv_bfloat16* q1 = q0 + 8*32;
        #pragma unroll
        for (int ks = 0; ks < 2; ++ks) {
            qa[ks][0] = *(const uint32_t*)(q0 + ks*16 + tg*2);
            qa[ks][1] = *(const uint32_t*)(q1 + ks*16 + tg*2);
            qa[ks][2] = *(const uint32_t*)(q0 + ks*16 + tg*2 + 8);
            qa[ks][3] = *(const uint32_t*)(q1 + ks*16 + tg*2 + 8);
        }
    }
    int qh0 = r0 / 48, qw0 = r0 - qh0*48;
    int qh1 = r1 / 48, qw1 = r1 - qh1*48;
    int qb0 = (qh0 - qh_min + 47)*BR + qw0 + 47;
    int qb1 = (qh1 - qh_min + 47)*BR + qw1 + 47;

    float o[4][4];
    #pragma unroll
    for (int i = 0; i < 4; ++i) { o[i][0]=o[i][1]=o[i][2]=o[i][3]=0.f; }
    float ls0 = 0.f, ls1 = 0.f;

    const __nv_bfloat16* kg = g_kb + (size_t)bh*LL*32;
    const __nv_bfloat16* vg = g_vt + (size_t)bh*32*LL;

    int kkey = tid >> 2, kseg = tid & 3;     // K staging roles
    int vd   = tid >> 3, vseg = tid & 7;     // V staging roles

    for (int kt = 0; kt < LL/64; ++kt) {
        __syncthreads();   // prev chunk compute done (also covers table staging at kt=0)
        // stage K [64x32] and V^T [32x64]
        {
            uint4 kv = *(const uint4*)(kg + (size_t)(kt*64 + kkey)*32 + kseg*8);
            *(uint4*)(KsB + kkey*80 + kseg*16) = kv;
            uint4 vv = *(const uint4*)(vg + (size_t)vd*LL + kt*64 + vseg*8);
            *(uint4*)(VtB + vd*144 + vseg*16) = vv;
        }
        __syncthreads();

        // ---- S = Q K^T : 8 n-tiles x 2 k-steps
        float S[8][4];
        #pragma unroll
        for (int nt = 0; nt < 8; ++nt) {
            S[nt][0]=S[nt][1]=S[nt][2]=S[nt][3]=0.f;
            const char* kb = KsB + (nt*8 + g)*80 + tg*4;
            uint32_t b0[2], b1[2];
            b0[0] = *(const uint32_t*)(kb);
            b0[1] = *(const uint32_t*)(kb + 16);
            b1[0] = *(const uint32_t*)(kb + 32);
            b1[1] = *(const uint32_t*)(kb + 48);
            mma16816(S[nt], qa[0], b0);
            mma16816(S[nt], qa[1], b1);
        }

        // ---- softmax (base-2, no max-sub) + pack P fragments in-register
        uint32_t pa[4][4];
        #pragma unroll
        for (int nt = 0; nt < 8; ++nt) {
            int2 ko = *(const int2*)&kOffS[kt*64 + nt*8 + tg*2];
            float p0 = ex2f(S[nt][0] + biasS[qb0 - ko.x]);
            float p1 = ex2f(S[nt][1] + biasS[qb0 - ko.y]);
            float p2 = ex2f(S[nt][2] + biasS[qb1 - ko.x]);
            float p3 = ex2f(S[nt][3] + biasS[qb1 - ko.y]);
            ls0 += p0 + p1;
            ls1 += p2 + p3;
            __nv_bfloat162 pp01 = __float22bfloat162_rn(make_float2(p0, p1));
            __nv_bfloat162 pp23 = __float22bfloat162_rn(make_float2(p2, p3));
            pa[nt >> 1][(nt & 1)*2 + 0] = *(uint32_t*)&pp01;
            pa[nt >> 1][(nt & 1)*2 + 1] = *(uint32_t*)&pp23;
        }

        // ---- O += P V : 4 k-steps x 4 n-tiles (d)
        #pragma unroll
        for (int ks = 0; ks < 4; ++ks) {
            #pragma unroll
            for (int nt = 0; nt < 4; ++nt) {
                const char* vba = VtB + (nt*8 + g)*144 + ks*32 + tg*4;
                uint32_t vb[2];
                vb[0] = *(const uint32_t*)(vba);
                vb[1] = *(const uint32_t*)(vba + 16);
                mma16816(o[nt], pa[ks], vb);
            }
        }
    }

    // ---- finalize: quad-reduce row sums, divide, write g_o ----------------
    ls0 += __shfl_xor_sync(0xFFFFFFFFu, ls0, 1);
    ls0 += __shfl_xor_sync(0xFFFFFFFFu, ls0, 2);
    ls1 += __shfl_xor_sync(0xFFFFFFFFu, ls1, 1);
    ls1 += __shfl_xor_sync(0xFFFFFFFFu, ls1, 2);
    float rd0 = 1.f / ls0, rd1 = 1.f / ls1;

    float* o0 = g_o + ((size_t)b*LL + r0)*256 + h*32 + tg*2;
    float* o1 = g_o + ((size_t)b*LL + r1)*256 + h*32 + tg*2;
    #pragma unroll
    for (int nt = 0; nt < 4; ++nt) {
        *(float2*)(o0 + nt*8) = make_float2(o[nt][0]*rd0, o[nt][1]*rd0);
        *(float2*)(o1 + nt*8) = make_float2(o[nt][2]*rd1, o[nt][3]*rd1);
    }
}

// ---------------------------------------------------------------------------
extern "C" void kernel_launch(void* const* d_in, const int* in_sizes, int n_in,
                              void* d_out, int out_size)
{
    const float* x      = (const float*)d_in[0];
    const float* ctx    = (const float*)d_in[1];
    const float* ln_x_w = (const float*)d_in[2];
    const float* ln_x_b = (const float*)d_in[3];
    const float* ln_c_w = (const float*)d_in[4];
    const float* ln_c_b = (const float*)d_in[5];
    const float* Wq     = (const float*)d_in[6];
    const float* bq     = (const float*)d_in[7];
    const float* Wk     = (const float*)d_in[8];
    const float* bk     = (const float*)d_in[9];
    const float* Wv     = (const float*)d_in[10];
    const float* bv     = (const float*)d_in[11];
    const float* Wp     = (const float*)d_in[12];
    const float* bp     = (const float*)d_in[13];
    const float* rel    = (const float*)d_in[14];
    float* out = (float*)d_out;

    dim3 lngrid(LL/32, BB);
    ln_kernel<0><<<lngrid, 256>>>(x,   ln_x_w, ln_x_b);
    ln_kernel<1><<<lngrid, 256>>>(ctx, ln_c_w, ln_c_b);
    bias_compact<<<(HEADS*BR*BR + 255)/256, 256>>>(rel);

    dim3 ggrid(BB*LL/64, INNER/64);
    gemm256<0><<<ggrid, 256>>>(Wq, bq, nullptr, nullptr);
    gemm256<1><<<ggrid, 256>>>(Wk, bk, nullptr, nullptr);
    gemm256<2><<<ggrid, 256>>>(Wv, bv, nullptr, nullptr);

    attn_hmma<<<dim3(LL/128, BB*HEADS), 256>>>();

    gemm256<3><<<ggrid, 256>>>(Wp, bp, out, x);
}

// round 6
// speedup vs baseline: 5.4944x; 1.7015x over previous
#include <cuda_runtime.h>
#include <cuda_bf16.h>
#include <math.h>
#include <cstdint>

#define HEADS 8
#define HEAD_DIM 32
#define CH 256
#define INNER 256
#define LL 2304
#define BB 4
#define TABLE_W 127     // 2*MAX_RES-1
#define BR 95           // 2*48-1
#define EPS 1e-6f
#define LOG2E 1.4426950408889634f
#define SC 0.25503486f  // (1/sqrt(32)) * log2(e)  -- folded into Q

// ---------------- scratch (device globals: no allocation allowed) ----------
__device__ __align__(128) __nv_bfloat16 g_xnb[BB*LL*CH];        // LN(x)   [b,l,c]
__device__ __align__(128) __nv_bfloat16 g_cnb[BB*LL*CH];        // LN(ctx) [b,l,c]
__device__ __align__(128) __nv_bfloat16 g_ob [BB*LL*INNER];     // attn out [b,l,c]
__device__ float g_biasc[HEADS*BR*BR];                          // bias * log2e
__device__ __align__(128) __nv_bfloat16 g_qb[BB*HEADS*LL*32];   // Q (pre-scaled by SC)
__device__ __align__(128) __nv_bfloat16 g_kb[BB*HEADS*LL*32];
__device__ __align__(128) __nv_bfloat16 g_vt[BB*HEADS*32*LL];   // V^T [bh][d][l]
__device__ __align__(128) __nv_bfloat16 g_wq[CH*INNER];
__device__ __align__(128) __nv_bfloat16 g_wk[CH*INNER];
__device__ __align__(128) __nv_bfloat16 g_wv[CH*INNER];
__device__ __align__(128) __nv_bfloat16 g_wp[CH*INNER];

// ---------------- small helpers --------------------------------------------
__device__ __forceinline__ float ex2f(float x) {
    float r;
    asm("ex2.approx.f32 %0, %1;" : "=f"(r) : "f"(x));
    return r;
}
__device__ __forceinline__ uint32_t bf2(float x, float y) {
    __nv_bfloat162 t = __float22bfloat162_rn(make_float2(x, y));
    return *(uint32_t*)&t;
}

// ---------------- HMMA m16n8k16 bf16 (sm_80+, legal at compute_103) --------
__device__ __forceinline__ void mma16816(float* c, const uint32_t* a, const uint32_t* b) {
    asm volatile(
        "mma.sync.aligned.m16n8k16.row.col.f32.bf16.bf16.f32 "
        "{%0,%1,%2,%3}, {%4,%5,%6,%7}, {%8,%9}, {%0,%1,%2,%3};"
        : "+f"(c[0]), "+f"(c[1]), "+f"(c[2]), "+f"(c[3])
        : "r"(a[0]), "r"(a[1]), "r"(a[2]), "r"(a[3]), "r"(b[0]), "r"(b[1]));
}
__device__ __forceinline__ void ldsm4(uint32_t* r, uint32_t addr) {
    asm volatile("ldmatrix.sync.aligned.m8n8.x4.shared.b16 {%0,%1,%2,%3}, [%4];"
        : "=r"(r[0]), "=r"(r[1]), "=r"(r[2]), "=r"(r[3]) : "r"(addr));
}
__device__ __forceinline__ uint32_t smem_u32(const void* p) {
    uint32_t a;
    asm("{ .reg .u64 t; cvta.to.shared.u64 t, %1; cvt.u32.u64 %0, t; }" : "=r"(a) : "l"(p));
    return a;
}

// ---------------- LayerNorm over C of NCHW -> bf16 [B, L, C] ---------------
template<int DST>
__global__ void ln_kernel(const float* __restrict__ in,
                          const float* __restrict__ w,
                          const float* __restrict__ bvec)
{
    __shared__ float s[CH*33];
    __shared__ float rsum[8][32];
    __shared__ float rsq[8][32];
    __shared__ float mu_s[32];
    __shared__ float rs_s[32];

    __nv_bfloat16* out = (DST == 0) ? g_xnb : g_cnb;

    int tx = threadIdx.x & 31;
    int ty = threadIdx.x >> 5;
    int b  = blockIdx.y;
    int l0 = blockIdx.x * 32;

    const float* inb = in + (size_t)b*CH*LL + l0;
    float sm = 0.f, sq = 0.f;
    #pragma unroll 4
    for (int cg = 0; cg < 32; ++cg) {
        int c = cg*8 + ty;
        float vv = inb[(size_t)c*LL + tx];
        s[c*33 + tx] = vv;
        sm += vv; sq += vv*vv;
    }
    rsum[ty][tx] = sm; rsq[ty][tx] = sq;
    __syncthreads();
    if (threadIdx.x < 32) {
        float a = 0.f, c2 = 0.f;
        #pragma unroll
        for (int j = 0; j < 8; ++j) { a += rsum[j][threadIdx.x]; c2 += rsq[j][threadIdx.x]; }
        float mu  = a * (1.f/CH);
        float var = c2 * (1.f/CH) - mu*mu;
        mu_s[threadIdx.x] = mu;
        rs_s[threadIdx.x] = rsqrtf(var + EPS);
    }
    __syncthreads();
    __nv_bfloat16* ob = out + ((size_t)b*LL + l0)*CH;
    #pragma unroll 4
    for (int i = threadIdx.x; i < 32*CH; i += 256) {
        int p = i >> 8, c = i & 255;
        float vv = s[c*33 + p];
        ob[(size_t)p*CH + c] =
            __float2bfloat16((vv - mu_s[p]) * rs_s[p] * w[c] + bvec[c]);
    }
}

// ---------------- prep: rel-bias compaction + fp32->bf16 weights -----------
__global__ void prep_kernel(const float* __restrict__ rel_table,
                            const float* __restrict__ Wq, const float* __restrict__ Wk,
                            const float* __restrict__ Wv, const float* __restrict__ Wp)
{
    int i = blockIdx.x*256 + threadIdx.x;
    if (i < CH*INNER) {
        g_wq[i] = __float2bfloat16(Wq[i]);
        g_wk[i] = __float2bfloat16(Wk[i]);
        g_wv[i] = __float2bfloat16(Wv[i]);
        g_wp[i] = __float2bfloat16(Wp[i]);
    }
    if (i < HEADS*BR*BR) {
        int h  = i / (BR*BR);
        int rr = i - h*(BR*BR);
        int dh = rr / BR;
        int dw = rr - dh*BR;
        int idx = (dh + 16)*TABLE_W + (dw + 16);
        g_biasc[i] = rel_table[idx*HEADS + h] * LOG2E;
    }
}

// ---------------- HMMA GEMM: C[M,256] = A[M,256] x W^T + bias --------------
// BM=128, BN=128, BK=64, 256 threads (8 warps; warp w -> m rows [w*16, +16))
// MODE 0: g_xnb x Wq -> g_qb (bf16 [bh][l][32], scaled by SC)
// MODE 1: g_cnb x Wk -> g_kb
// MODE 2: g_cnb x Wv -> g_vt (bf16 transposed via smem)
// MODE 3: g_ob  x Wp -> Cout = x + . (NCHW f32 via smem transpose)
#define HG_B  18432           // Bsm offset (A tile: 128 rows x 144B)
#define HG_ST 36864           // staging bytes
#define HG_TR 67584           // trbuf bytes: 128 x 132 f32
template<int MODE>
__global__ __launch_bounds__(256) void hgemm(const float* __restrict__ bias,
                                             float* __restrict__ Cout,
                                             const float* __restrict__ resid)
{
    extern __shared__ char sm[];
    const __nv_bfloat16* A =
        (MODE == 0) ? g_xnb : (MODE == 3) ? g_ob : g_cnb;
    const __nv_bfloat16* Wb =
        (MODE == 0) ? g_wq : (MODE == 1) ? g_wk : (MODE == 2) ? g_wv : g_wp;

    int tid = threadIdx.x;
    int w = tid >> 5, lane = tid & 31;
    int g = lane >> 2, tg = lane & 3;
    int m0 = blockIdx.x * 128, n0 = blockIdx.y * 128;

    // staging roles
    int srow = tid >> 1, shalf = tid & 1;
    const uint4* agp = (const uint4*)(A  + (size_t)(m0 + srow)*256 + shalf*32);
    const uint4* bgp = (const uint4*)(Wb + (size_t)(n0 + srow)*256 + shalf*32);
    uint4* asp = (uint4*)(sm + srow*144 + shalf*64);
    uint4* bsp = (uint4*)(sm + HG_B + srow*144 + shalf*64);

    // ldmatrix lane address bases
    uint32_t sb = smem_u32(sm);
    int tA = lane >> 3, rA = lane & 7;
    uint32_t aBase = sb + (uint32_t)((w*16 + (tA & 1)*8 + rA)*144 + (tA >> 1)*16);
    uint32_t bBase = sb + HG_B + (uint32_t)(((tA >> 1)*8 + rA)*144 + (tA & 1)*16);

    float c[16][4];
    #pragma unroll
    for (int i = 0; i < 16; ++i) { c[i][0]=c[i][1]=c[i][2]=c[i][3]=0.f; }

    for (int kc = 0; kc < 4; ++kc) {
        __syncthreads();
        #pragma unroll
        for (int j = 0; j < 4; ++j) asp[j] = agp[kc*8 + j];
        #pragma unroll
        for (int j = 0; j < 4; ++j) bsp[j] = bgp[kc*8 + j];
        __syncthreads();
        #pragma unroll
        for (int ks = 0; ks < 4; ++ks) {
            uint32_t a[4];
            ldsm4(a, aBase + ks*32);
            #pragma unroll
            for (int p = 0; p < 8; ++p) {
                uint32_t bb[4];
                ldsm4(bb, bBase + p*2304 + ks*32);
                mma16816(c[2*p],     a, bb);
                mma16816(c[2*p + 1], a, bb + 2);
            }
        }
    }

    int b  = m0 / LL;                 // 128-row tiles never straddle batches
    int l0 = m0 - b*LL;
    int r0 = l0 + w*16 + g, r1 = r0 + 8;

    if (MODE == 0 || MODE == 1) {
        __nv_bfloat16* dst = (MODE == 0) ? g_qb : g_kb;
        const float scl = (MODE == 0) ? SC : 1.0f;
        #pragma unroll
        for (int nt = 0; nt < 16; ++nt) {
            int n = n0 + nt*8 + tg*2;
            float2 bb = *(const float2*)(bias + n);
            int hh = n >> 5, d0 = n & 31;
            uint32_t u0 = bf2((c[nt][0]+bb.x)*scl, (c[nt][1]+bb.y)*scl);
            uint32_t u1 = bf2((c[nt][2]+bb.x)*scl, (c[nt][3]+bb.y)*scl);
            *(uint32_t*)(&dst[((size_t)(b*8 + hh)*LL + r0)*32 + d0]) = u0;
            *(uint32_t*)(&dst[((size_t)(b*8 + hh)*LL + r1)*32 + d0]) = u1;
        }
    } else {
        // transpose through smem (union with staging tiles)
        __syncthreads();
        float* tr = (float*)sm;
        int lr0 = w*16 + g, lr1 = lr0 + 8;
        #pragma unroll
        for (int nt = 0; nt < 16; ++nt) {
            int nl = nt*8 + tg*2;
            tr[nl*132 + lr0]       = c[nt][0];
            tr[(nl + 1)*132 + lr0] = c[nt][1];
            tr[nl*132 + lr1]       = c[nt][2];
            tr[(nl + 1)*132 + lr1] = c[nt][3];
        }
        __syncthreads();
        int n = tid >> 1, lh = (tid & 1)*64;
        int gn = n0 + n;
        float bj = bias[gn];
        const float* trp = tr + n*132 + lh;
        if (MODE == 3) {
            size_t ad = ((size_t)b*256 + gn)*LL + l0 + lh;
            #pragma unroll
            for (int j = 0; j < 16; ++j) {
                float4 xv = ((const float4*)(resid + ad))[j];
                float4 tv = *(const float4*)(trp + j*4);
                ((float4*)(Cout + ad))[j] = make_float4(
                    xv.x + tv.x + bj, xv.y + tv.y + bj,
                    xv.z + tv.z + bj, xv.w + tv.w + bj);
            }
        } else {  // MODE 2 -> g_vt bf16 [bh][d][l]
            int hh = gn >> 5, d = gn & 31;
            __nv_bfloat16* vd = g_vt + ((size_t)(b*8 + hh)*32 + d)*LL + l0 + lh;
            #pragma unroll
            for (int j = 0; j < 8; ++j) {
                float4 t0 = *(const float4*)(trp + j*8);
                float4 t1 = *(const float4*)(trp + j*8 + 4);
                uint4 u;
                u.x = bf2(t0.x + bj, t0.y + bj);
                u.y = bf2(t0.z + bj, t0.w + bj);
                u.z = bf2(t1.x + bj, t1.y + bj);
                u.w = bf2(t1.z + bj, t1.w + bj);
                *(uint4*)(vd + j*8) = u;
            }
        }
    }
}

// ---------------- HMMA flash attention -------------------------------------
// grid (LL/128, BB*HEADS), 256 threads (8 warps). Warp w owns q-rows
// [l0 + w*16, +16) as one m16 tile. Keys iterated in 64-chunks.
__global__ void __launch_bounds__(256) attn_hmma()
{
    __shared__ __align__(16) char KsB[64*80];     // K chunk [key][d] pitch 80B
    __shared__ __align__(16) char VtB[32*144];    // V^T chunk [d][key] pitch 144B
    __shared__ float biasS[52*BR];                // bias sub-table (<=51 rows used)
    __shared__ int   kOffS[LL];                   // kh*95+kw per key

    int tid = threadIdx.x;
    int w = tid >> 5, lane = tid & 31;
    int g = lane >> 2, tg = lane & 3;
    int bh = blockIdx.y;
    int b = bh >> 3, h = bh & 7;
    int l0 = blockIdx.x * 128;

    for (int i = tid; i < LL; i += 256) {
        int kh = i / 48;
        kOffS[i] = kh*BR + (i - kh*48);
    }
    int qh_min = l0 / 48;
    {
        int qh_max = (l0 + 127) / 48;
        int rows = qh_max - qh_min + 48;          // <= 51
        const float* bc = g_biasc + h*BR*BR + qh_min*BR;
        for (int i = tid; i < rows*BR; i += 256) biasS[i] = bc[i];
    }

    int r0 = l0 + w*16 + g;
    int r1 = r0 + 8;
    uint32_t qa[2][4];
    {
        const __nv_bfloat16* q0 = g_qb + ((size_t)bh*LL + r0)*32;
        const __nv_bfloat16* q1 = q0 + 8*32;
        #pragma unroll
        for (int ks = 0; ks < 2; ++ks) {
            qa[ks][0] = *(const uint32_t*)(q0 + ks*16 + tg*2);
            qa[ks][1] = *(const uint32_t*)(q1 + ks*16 + tg*2);
            qa[ks][2] = *(const uint32_t*)(q0 + ks*16 + tg*2 + 8);
            qa[ks][3] = *(const uint32_t*)(q1 + ks*16 + tg*2 + 8);
        }
    }
    int qh0 = r0 / 48, qw0 = r0 - qh0*48;
    int qh1 = r1 / 48, qw1 = r1 - qh1*48;
    int qb0 = (qh0 - qh_min + 47)*BR + qw0 + 47;
    int qb1 = (qh1 - qh_min + 47)*BR + qw1 + 47;

    float o[4][4];
    #pragma unroll
    for (int i = 0; i < 4; ++i) { o[i][0]=o[i][1]=o[i][2]=o[i][3]=0.f; }
    float ls0 = 0.f, ls1 = 0.f;

    const __nv_bfloat16* kg = g_kb + (size_t)bh*LL*32;
    const __nv_bfloat16* vg = g_vt + (size_t)bh*32*LL;

    int kkey = tid >> 2, kseg = tid & 3;
    int vd   = tid >> 3, vseg = tid & 7;

    for (int kt = 0; kt < LL/64; ++kt) {
        __syncthreads();
        {
            uint4 kv = *(const uint4*)(kg + (size_t)(kt*64 + kkey)*32 + kseg*8);
            *(uint4*)(KsB + kkey*80 + kseg*16) = kv;
            uint4 vv = *(const uint4*)(vg + (size_t)vd*LL + kt*64 + vseg*8);
            *(uint4*)(VtB + vd*144 + vseg*16) = vv;
        }
        __syncthreads();

        float S[8][4];
        #pragma unroll
        for (int nt = 0; nt < 8; ++nt) {
            S[nt][0]=S[nt][1]=S[nt][2]=S[nt][3]=0.f;
            const char* kb = KsB + (nt*8 + g)*80 + tg*4;
            uint32_t b0[2], b1[2];
            b0[0] = *(const uint32_t*)(kb);
            b0[1] = *(const uint32_t*)(kb + 16);
            b1[0] = *(const uint32_t*)(kb + 32);
            b1[1] = *(const uint32_t*)(kb + 48);
            mma16816(S[nt], qa[0], b0);
            mma16816(S[nt], qa[1], b1);
        }

        uint32_t pa[4][4];
        #pragma unroll
        for (int nt = 0; nt < 8; ++nt) {
            int2 ko = *(const int2*)&kOffS[kt*64 + nt*8 + tg*2];
            float p0 = ex2f(S[nt][0] + biasS[qb0 - ko.x]);
            float p1 = ex2f(S[nt][1] + biasS[qb0 - ko.y]);
            float p2 = ex2f(S[nt][2] + biasS[qb1 - ko.x]);
            float p3 = ex2f(S[nt][3] + biasS[qb1 - ko.y]);
            ls0 += p0 + p1;
            ls1 += p2 + p3;
            pa[nt >> 1][(nt & 1)*2 + 0] = bf2(p0, p1);
            pa[nt >> 1][(nt & 1)*2 + 1] = bf2(p2, p3);
        }

        #pragma unroll
        for (int ks = 0; ks < 4; ++ks) {
            #pragma unroll
            for (int nt = 0; nt < 4; ++nt) {
                const char* vba = VtB + (nt*8 + g)*144 + ks*32 + tg*4;
                uint32_t vb[2];
                vb[0] = *(const uint32_t*)(vba);
                vb[1] = *(const uint32_t*)(vba + 16);
                mma16816(o[nt], pa[ks], vb);
            }
        }
    }

    ls0 += __shfl_xor_sync(0xFFFFFFFFu, ls0, 1);
    ls0 += __shfl_xor_sync(0xFFFFFFFFu, ls0, 2);
    ls1 += __shfl_xor_sync(0xFFFFFFFFu, ls1, 1);
    ls1 += __shfl_xor_sync(0xFFFFFFFFu, ls1, 2);
    float rd0 = 1.f / ls0, rd1 = 1.f / ls1;

    __nv_bfloat16* o0 = g_ob + ((size_t)b*LL + r0)*256 + h*32 + tg*2;
    __nv_bfloat16* o1 = g_ob + ((size_t)b*LL + r1)*256 + h*32 + tg*2;
    #pragma unroll
    for (int nt = 0; nt < 4; ++nt) {
        *(uint32_t*)(o0 + nt*8) = bf2(o[nt][0]*rd0, o[nt][1]*rd0);
        *(uint32_t*)(o1 + nt*8) = bf2(o[nt][2]*rd1, o[nt][3]*rd1);
    }
}

// ---------------------------------------------------------------------------
extern "C" void kernel_launch(void* const* d_in, const int* in_sizes, int n_in,
                              void* d_out, int out_size)
{
    const float* x      = (const float*)d_in[0];
    const float* ctx    = (const float*)d_in[1];
    const float* ln_x_w = (const float*)d_in[2];
    const float* ln_x_b = (const float*)d_in[3];
    const float* ln_c_w = (const float*)d_in[4];
    const float* ln_c_b = (const float*)d_in[5];
    const float* Wq     = (const float*)d_in[6];
    const float* bq     = (const float*)d_in[7];
    const float* Wk     = (const float*)d_in[8];
    const float* bk     = (const float*)d_in[9];
    const float* Wv     = (const float*)d_in[10];
    const float* bv     = (const float*)d_in[11];
    const float* Wp     = (const float*)d_in[12];
    const float* bp     = (const float*)d_in[13];
    const float* rel    = (const float*)d_in[14];
    float* out = (float*)d_out;

    static int attr_done = 0;
    if (!attr_done) {
        cudaFuncSetAttribute(hgemm<2>, cudaFuncAttributeMaxDynamicSharedMemorySize, HG_TR);
        cudaFuncSetAttribute(hgemm<3>, cudaFuncAttributeMaxDynamicSharedMemorySize, HG_TR);
        attr_done = 1;
    }

    dim3 lngrid(LL/32, BB);
    ln_kernel<0><<<lngrid, 256>>>(x,   ln_x_w, ln_x_b);
    ln_kernel<1><<<lngrid, 256>>>(ctx, ln_c_w, ln_c_b);
    prep_kernel<<<(CH*INNER + 255)/256, 256>>>(rel, Wq, Wk, Wv, Wp);

    dim3 ggrid(BB*LL/128, INNER/128);
    hgemm<0><<<ggrid, 256, HG_ST>>>(bq, nullptr, nullptr);
    hgemm<1><<<ggrid, 256, HG_ST>>>(bk, nullptr, nullptr);
    hgemm<2><<<ggrid, 256, HG_TR>>>(bv, nullptr, nullptr);

    attn_hmma<<<dim3(LL/128, BB*HEADS), 256>>>();

    hgemm<3><<<ggrid, 256, HG_TR>>>(bp, out, x);
}

// round 12
// speedup vs baseline: 5.8911x; 1.0722x over previous
#include <cuda_runtime.h>
#include <cuda_bf16.h>
#include <math.h>
#include <cstdint>

#define HEADS 8
#define HEAD_DIM 32
#define CH 256
#define INNER 256
#define LL 2304
#define BB 4
#define TABLE_W 127     // 2*MAX_RES-1
#define BR 95           // 2*48-1
#define EPS 1e-6f
#define LOG2E 1.4426950408889634f
#define SC 0.25503486f  // (1/sqrt(32)) * log2(e)  -- folded into Q

// ---------------- scratch (device globals: no allocation allowed) ----------
__device__ __align__(128) __nv_bfloat16 g_xnb[BB*LL*CH];        // LN(x)   [b,l,c]
__device__ __align__(128) __nv_bfloat16 g_cnb[BB*LL*CH];        // LN(ctx) [b,l,c]
__device__ __align__(128) __nv_bfloat16 g_ob [BB*LL*INNER];     // attn out [b,l,c]
__device__ float g_biasc[HEADS*BR*BR];                          // bias * log2e
__device__ __align__(128) __nv_bfloat16 g_qb[BB*HEADS*LL*32];   // Q (pre-scaled by SC)
__device__ __align__(128) __nv_bfloat16 g_kb[BB*HEADS*LL*32];
__device__ __align__(128) __nv_bfloat16 g_vt[BB*HEADS*32*LL];   // V^T [bh][d][l]
__device__ __align__(128) __nv_bfloat16 g_wq[CH*INNER];
__device__ __align__(128) __nv_bfloat16 g_wk[CH*INNER];
__device__ __align__(128) __nv_bfloat16 g_wv[CH*INNER];
__device__ __align__(128) __nv_bfloat16 g_wp[CH*INNER];

// ---------------- small helpers --------------------------------------------
__device__ __forceinline__ float ex2f(float x) {
    float r;
    asm("ex2.approx.f32 %0, %1;" : "=f"(r) : "f"(x));
    return r;
}
__device__ __forceinline__ uint32_t bf2(float x, float y) {
    __nv_bfloat162 t = __float22bfloat162_rn(make_float2(x, y));
    return *(uint32_t*)&t;
}
__device__ __forceinline__ void mma16816(float* c, const uint32_t* a, const uint32_t* b) {
    asm volatile(
        "mma.sync.aligned.m16n8k16.row.col.f32.bf16.bf16.f32 "
        "{%0,%1,%2,%3}, {%4,%5,%6,%7}, {%8,%9}, {%0,%1,%2,%3};"
        : "+f"(c[0]), "+f"(c[1]), "+f"(c[2]), "+f"(c[3])
        : "r"(a[0]), "r"(a[1]), "r"(a[2]), "r"(a[3]), "r"(b[0]), "r"(b[1]));
}
__device__ __forceinline__ void ldsm4(uint32_t* r, uint32_t addr) {
    asm volatile("ldmatrix.sync.aligned.m8n8.x4.shared.b16 {%0,%1,%2,%3}, [%4];"
        : "=r"(r[0]), "=r"(r[1]), "=r"(r[2]), "=r"(r[3]) : "r"(addr));
}
__device__ __forceinline__ uint32_t smem_u32(const void* p) {
    uint32_t a;
    asm("{ .reg .u64 t; cvta.to.shared.u64 t, %1; cvt.u32.u64 %0, t; }" : "=r"(a) : "l"(p));
    return a;
}
__device__ __forceinline__ void cpa16(uint32_t dst, const void* src) {
    asm volatile("cp.async.cg.shared.global [%0], [%1], 16;"
        :: "r"(dst), "l"(__cvta_generic_to_global(src)) : "memory");
}
#define CP_COMMIT() asm volatile("cp.async.commit_group;" ::: "memory")
#define CP_WAIT(n)  asm volatile("cp.async.wait_group %0;" :: "n"(n) : "memory")

// ---------------- LayerNorm over C of NCHW -> bf16 [B, L, C] (fused x/ctx) -
__global__ void ln_fused(const float* __restrict__ x, const float* __restrict__ ctx,
                         const float* __restrict__ wx, const float* __restrict__ bx,
                         const float* __restrict__ wc, const float* __restrict__ bc)
{
    __shared__ float s[CH*33];
    __shared__ float rsum[8][32];
    __shared__ float rsq[8][32];
    __shared__ float mu_s[32];
    __shared__ float rs_s[32];

    const float* in = blockIdx.z ? ctx : x;
    const float* w  = blockIdx.z ? wc : wx;
    const float* bvec = blockIdx.z ? bc : bx;
    __nv_bfloat16* out = blockIdx.z ? g_cnb : g_xnb;

    int tx = threadIdx.x & 31;
    int ty = threadIdx.x >> 5;
    int b  = blockIdx.y;
    int l0 = blockIdx.x * 32;

    const float* inb = in + (size_t)b*CH*LL + l0;
    float sm = 0.f, sq = 0.f;
    #pragma unroll 4
    for (int cg = 0; cg < 32; ++cg) {
        int c = cg*8 + ty;
        float vv = inb[(size_t)c*LL + tx];
        s[c*33 + tx] = vv;
        sm += vv; sq += vv*vv;
    }
    rsum[ty][tx] = sm; rsq[ty][tx] = sq;
    __syncthreads();
    if (threadIdx.x < 32) {
        float a = 0.f, c2 = 0.f;
        #pragma unroll
        for (int j = 0; j < 8; ++j) { a += rsum[j][threadIdx.x]; c2 += rsq[j][threadIdx.x]; }
        float mu  = a * (1.f/CH);
        float var = c2 * (1.f/CH) - mu*mu;
        mu_s[threadIdx.x] = mu;
        rs_s[threadIdx.x] = rsqrtf(var + EPS);
    }
    __syncthreads();
    __nv_bfloat16* ob = out + ((size_t)b*LL + l0)*CH;
    #pragma unroll 4
    for (int i = threadIdx.x; i < 32*CH; i += 256) {
        int p = i >> 8, c = i & 255;
        float vv = s[c*33 + p];
        ob[(size_t)p*CH + c] =
            __float2bfloat16((vv - mu_s[p]) * rs_s[p] * w[c] + bvec[c]);
    }
}

// ---------------- prep: rel-bias compaction + fp32->bf16 weights -----------
// NOTE: grid must cover max(CH*INNER, HEADS*BR*BR) = 72200.
__global__ void prep_kernel(const float* __restrict__ rel_table,
                            const float* __restrict__ Wq, const float* __restrict__ Wk,
                            const float* __restrict__ Wv, const float* __restrict__ Wp)
{
    int i = blockIdx.x*256 + threadIdx.x;
    if (i < CH*INNER) {
        g_wq[i] = __float2bfloat16(Wq[i]);
        g_wk[i] = __float2bfloat16(Wk[i]);
        g_wv[i] = __float2bfloat16(Wv[i]);
        g_wp[i] = __float2bfloat16(Wp[i]);
    }
    if (i < HEADS*BR*BR) {
        int h  = i / (BR*BR);
        int rr = i - h*(BR*BR);
        int dh = rr / BR;
        int dw = rr - dh*BR;
        int idx = (dh + 16)*TABLE_W + (dw + 16);
        g_biasc[i] = rel_table[idx*HEADS + h] * LOG2E;
    }
}

// ---------------- HMMA GEMM, cp.async double-buffered ----------------------
// BM=128, BN=128, BK=64. PROJ=0: fused QKV (mode = blockIdx.z 0..2).
// PROJ=1: out-projection with residual (NCHW f32).
#define HG_BOFF 18432          // B tile offset within one buffer
#define HG_BUF  36864          // one double-buffer slot (A+B tiles)
#define HG_DYN  73728          // 2 buffers; transpose epilogue reuses [0, 67584)
template<int PROJ>
__global__ __launch_bounds__(256) void hgemm(const float* __restrict__ bias0,
                                             const float* __restrict__ bias1,
                                             const float* __restrict__ bias2,
                                             float* __restrict__ Cout,
                                             const float* __restrict__ resid)
{
    extern __shared__ char smc[];
    int mode = PROJ ? 3 : blockIdx.z;
    const __nv_bfloat16* A  = (mode == 0) ? g_xnb : (mode == 3) ? g_ob : g_cnb;
    const __nv_bfloat16* Wb = (mode == 0) ? g_wq : (mode == 1) ? g_wk
                            : (mode == 2) ? g_wv : g_wp;
    const float* bias = PROJ ? bias0
                      : (mode == 0 ? bias0 : (mode == 1 ? bias1 : bias2));

    int tid = threadIdx.x;
    int w = tid >> 5, lane = tid & 31;
    int g = lane >> 2, tg = lane & 3;
    int m0 = blockIdx.x * 128, n0 = blockIdx.y * 128;

    // cp.async staging roles: thread -> (row, 64B half), 4x16B each of A and B
    int srow = tid >> 1, shalf = tid & 1;
    const __nv_bfloat16* agp = A  + (size_t)(m0 + srow)*256 + shalf*32;
    const __nv_bfloat16* bgp = Wb + (size_t)(n0 + srow)*256 + shalf*32;
    uint32_t sb = smem_u32(smc);
    uint32_t aDst = sb + (uint32_t)(srow*144 + shalf*64);
    uint32_t bDst = aDst + HG_BOFF;

    // ldmatrix lane bases
    int tA = lane >> 3, rA = lane & 7;
    uint32_t aBase = sb + (uint32_t)((w*16 + (tA & 1)*8 + rA)*144 + (tA >> 1)*16);
    uint32_t bBase = sb + HG_BOFF + (uint32_t)(((tA >> 1)*8 + rA)*144 + (tA & 1)*16);

    float c[16][4];
    #pragma unroll
    for (int i = 0; i < 16; ++i) { c[i][0]=c[i][1]=c[i][2]=c[i][3]=0.f; }

    // preload chunk 0 into buffer 0
    #pragma unroll
    for (int j = 0; j < 4; ++j) {
        cpa16(aDst + j*16, agp + j*8);
        cpa16(bDst + j*16, bgp + j*8);
    }
    CP_COMMIT();

    #pragma unroll
    for (int kc = 0; kc < 4; ++kc) {
        __syncthreads();                       // all prior compute done
        if (kc < 3) {
            uint32_t nb = (uint32_t)(((kc + 1) & 1) * HG_BUF);
            #pragma unroll
            for (int j = 0; j < 4; ++j) {
                cpa16(aDst + nb + j*16, agp + (kc+1)*64 + j*8);
                cpa16(bDst + nb + j*16, bgp + (kc+1)*64 + j*8);
            }
            CP_COMMIT();
            CP_WAIT(1);
        } else {
            CP_WAIT(0);
        }
        __syncthreads();                       // staged chunk kc visible

        uint32_t bo = (uint32_t)((kc & 1) * HG_BUF);
        #pragma unroll
        for (int ks = 0; ks < 4; ++ks) {
            uint32_t a[4];
            ldsm4(a, aBase + bo + ks*32);
            #pragma unroll
            for (int p = 0; p < 8; ++p) {
                uint32_t bb[4];
                ldsm4(bb, bBase + bo + p*2304 + ks*32);
                mma16816(c[2*p],     a, bb);
                mma16816(c[2*p + 1], a, bb + 2);
            }
        }
    }

    int b  = m0 / LL;                 // 128-row tiles never straddle batches
    int l0 = m0 - b*LL;
    int r0 = l0 + w*16 + g, r1 = r0 + 8;

    if (!PROJ && mode <= 1) {
        __nv_bfloat16* dst = (mode == 0) ? g_qb : g_kb;
        const float scl = (mode == 0) ? SC : 1.0f;
        #pragma unroll
        for (int nt = 0; nt < 16; ++nt) {
            int n = n0 + nt*8 + tg*2;
            float2 bb = *(const float2*)(bias + n);
            int hh = n >> 5, d0 = n & 31;
            uint32_t u0 = bf2((c[nt][0]+bb.x)*scl, (c[nt][1]+bb.y)*scl);
            uint32_t u1 = bf2((c[nt][2]+bb.x)*scl, (c[nt][3]+bb.y)*scl);
            *(uint32_t*)(&dst[((size_t)(b*8 + hh)*LL + r0)*32 + d0]) = u0;
            *(uint32_t*)(&dst[((size_t)(b*8 + hh)*LL + r1)*32 + d0]) = u1;
        }
    } else {
        // transpose through smem (reuse staging buffers)
        __syncthreads();
        float* tr = (float*)smc;
        int lr0 = w*16 + g, lr1 = lr0 + 8;
        #pragma unroll
        for (int nt = 0; nt < 16; ++nt) {
            int nl = nt*8 + tg*2;
            tr[nl*132 + lr0]       = c[nt][0];
            tr[(nl + 1)*132 + lr0] = c[nt][1];
            tr[nl*132 + lr1]       = c[nt][2];
            tr[(nl + 1)*132 + lr1] = c[nt][3];
        }
        __syncthreads();
        int n = tid >> 1, lh = (tid & 1)*64;
        int gn = n0 + n;
        float bj = bias[gn];
        const float* trp = tr + n*132 + lh;
        if (PROJ) {
            size_t ad = ((size_t)b*256 + gn)*LL + l0 + lh;
            #pragma unroll
            for (int j = 0; j < 16; ++j) {
                float4 xv = ((const float4*)(resid + ad))[j];
                float4 tv = *(const float4*)(trp + j*4);
                ((float4*)(Cout + ad))[j] = make_float4(
                    xv.x + tv.x + bj, xv.y + tv.y + bj,
                    xv.z + tv.z + bj, xv.w + tv.w + bj);
            }
        } else {  // mode 2 -> g_vt bf16 [bh][d][l]
            int hh = gn >> 5, d = gn & 31;
            __nv_bfloat16* vd = g_vt + ((size_t)(b*8 + hh)*32 + d)*LL + l0 + lh;
            #pragma unroll
            for (int j = 0; j < 8; ++j) {
                float4 t0 = *(const float4*)(trp + j*8);
                float4 t1 = *(const float4*)(trp + j*8 + 4);
                uint4 u;
                u.x = bf2(t0.x + bj, t0.y + bj);
                u.y = bf2(t0.z + bj, t0.w + bj);
                u.z = bf2(t1.x + bj, t1.y + bj);
                u.w = bf2(t1.z + bj, t1.w + bj);
                *(uint4*)(vd + j*8) = u;
            }
        }
    }
}

// ---------------- HMMA flash attention (ldmatrix + cp.async) ---------------
// grid (LL/128, BB*HEADS), 256 threads (8 warps). Warp w owns q-rows
// [l0 + w*16, +16). Keys in 64-chunks, double-buffered.
__global__ void __launch_bounds__(256) attn_hmma()
{
    __shared__ __align__(16) char KsB[2][64*80];   // [key][d] pitch 80B
    __shared__ __align__(16) char VtB[2][32*144];  // [d][key] pitch 144B
    __shared__ float biasS[52*BR];
    __shared__ int   kOffS[LL];

    int tid = threadIdx.x;
    int w = tid >> 5, lane = tid & 31;
    int g = lane >> 2, tg = lane & 3;
    int bh = blockIdx.y;
    int b = bh >> 3, h = bh & 7;
    int l0 = blockIdx.x * 128;

    for (int i = tid; i < LL; i += 256) {
        int kh = i / 48;
        kOffS[i] = kh*BR + (i - kh*48);
    }
    int qh_min = l0 / 48;
    {
        int qh_max = (l0 + 127) / 48;
        int rows = qh_max - qh_min + 48;          // <= 51
        const float* bc = g_biasc + h*BR*BR + qh_min*BR;
        for (int i = tid; i < rows*BR; i += 256) biasS[i] = bc[i];
    }

    int r0 = l0 + w*16 + g;
    int r1 = r0 + 8;
    uint32_t qa[2][4];
    {
        const __nv_bfloat16* q0 = g_qb + ((size_t)bh*LL + r0)*32;
        const __nv_bfloat16* q1 = q0 + 8*32;
        #pragma unroll
        for (int ks = 0; ks < 2; ++ks) {
            qa[ks][0] = *(const uint32_t*)(q0 + ks*16 + tg*2);
            qa[ks][1] = *(const uint32_t*)(q1 + ks*16 + tg*2);
            qa[ks][2] = *(const uint32_t*)(q0 + ks*16 + tg*2 + 8);
            qa[ks][3] = *(const uint32_t*)(q1 + ks*16 + tg*2 + 8);
        }
    }
    int qh0 = r0 / 48, qw0 = r0 - qh0*48;
    int qh1 = r1 / 48, qw1 = r1 - qh1*48;
    int qb0 = (qh0 - qh_min + 47)*BR + qw0 + 47;
    int qb1 = (qh1 - qh_min + 47)*BR + qw1 + 47;

    float o[4][4];
    #pragma unroll
    for (int i = 0; i < 4; ++i) { o[i][0]=o[i][1]=o[i][2]=o[i][3]=0.f; }
    float ls0 = 0.f, ls1 = 0.f;

    const __nv_bfloat16* kg = g_kb + (size_t)bh*LL*32;
    const __nv_bfloat16* vg = g_vt + (size_t)bh*32*LL;

    // cp.async roles: 1 x 16B per thread for K and V each
    int kkey = tid >> 2, kseg = tid & 3;
    int vd   = tid >> 3, vseg = tid & 7;
    uint32_t kDst = smem_u32(&KsB[0][0]) + (uint32_t)(kkey*80 + kseg*16);
    uint32_t vDst = smem_u32(&VtB[0][0]) + (uint32_t)(vd*144 + vseg*16);

    // ldmatrix lane bases: lane = t*8 + r -> tile t, row r
    int t4 = lane >> 3, r8 = lane & 7;
    uint32_t kAdr0 = smem_u32(&KsB[0][0]) + (uint32_t)((8*(t4 >> 1) + r8)*80  + (t4 & 1)*16);
    uint32_t vAdr0 = smem_u32(&VtB[0][0]) + (uint32_t)((8*(t4 >> 1) + r8)*144 + (t4 & 1)*16);

    // preload chunk 0
    cpa16(kDst, kg + (size_t)kkey*32 + kseg*8);
    cpa16(vDst, vg + (size_t)vd*LL + vseg*8);
    CP_COMMIT();

    for (int kt = 0; kt < LL/64; ++kt) {
        int cur = kt & 1;
        __syncthreads();                       // prev compute done everywhere
        if (kt < LL/64 - 1) {
            uint32_t nxt = (uint32_t)(cur ^ 1);
            cpa16(kDst + nxt*5120, kg + (size_t)((kt+1)*64 + kkey)*32 + kseg*8);
            cpa16(vDst + nxt*4608, vg + (size_t)vd*LL + (kt+1)*64 + vseg*8);
            CP_COMMIT();
            CP_WAIT(1);
        } else {
            CP_WAIT(0);
        }
        __syncthreads();                       // chunk kt visible to all

        uint32_t kAdr = kAdr0 + (uint32_t)(cur*5120);
        uint32_t vAdr = vAdr0 + (uint32_t)(cur*4608);

        // ---- S = Q K^T : 8 ldsm.x4 + 16 HMMA
        float S[8][4];
        #pragma unroll
        for (int ntp = 0; ntp < 4; ++ntp) {
            S[2*ntp][0]=S[2*ntp][1]=S[2*ntp][2]=S[2*ntp][3]=0.f;
            S[2*ntp+1][0]=S[2*ntp+1][1]=S[2*ntp+1][2]=S[2*ntp+1][3]=0.f;
            #pragma unroll
            for (int ks = 0; ks < 2; ++ks) {
                uint32_t bb[4];
                ldsm4(bb, kAdr + ntp*1280 + ks*32);
                mma16816(S[2*ntp],     qa[ks], bb);
                mma16816(S[2*ntp + 1], qa[ks], bb + 2);
            }
        }

        // ---- softmax (base-2, no max-sub) + pack P fragments
        uint32_t pa[4][4];
        #pragma unroll
        for (int nt = 0; nt < 8; ++nt) {
            int2 ko = *(const int2*)&kOffS[kt*64 + nt*8 + tg*2];
            float p0 = ex2f(S[nt][0] + biasS[qb0 - ko.x]);
            float p1 = ex2f(S[nt][1] + biasS[qb0 - ko.y]);
            float p2 = ex2f(S[nt][2] + biasS[qb1 - ko.x]);
            float p3 = ex2f(S[nt][3] + biasS[qb1 - ko.y]);
            ls0 += p0 + p1;
            ls1 += p2 + p3;
            pa[nt >> 1][(nt & 1)*2 + 0] = bf2(p0, p1);
            pa[nt >> 1][(nt & 1)*2 + 1] = bf2(p2, p3);
        }

        // ---- O += P V : 8 ldsm.x4 + 16 HMMA
        #pragma unroll
        for (int ntp = 0; ntp < 2; ++ntp) {
            #pragma unroll
            for (int ks = 0; ks < 4; ++ks) {
                uint32_t bb[4];
                ldsm4(bb, vAdr + ntp*2304 + ks*32);
                mma16816(o[2*ntp],     pa[ks], bb);
                mma16816(o[2*ntp + 1], pa[ks], bb + 2);
            }
        }
    }

    ls0 += __shfl_xor_sync(0xFFFFFFFFu, ls0, 1);
    ls0 += __shfl_xor_sync(0xFFFFFFFFu, ls0, 2);
    ls1 += __shfl_xor_sync(0xFFFFFFFFu, ls1, 1);
    ls1 += __shfl_xor_sync(0xFFFFFFFFu, ls1, 2);
    float rd0 = 1.f / ls0, rd1 = 1.f / ls1;

    __nv_bfloat16* o0 = g_ob + ((size_t)b*LL + r0)*256 + h*32 + tg*2;
    __nv_bfloat16* o1 = g_ob + ((size_t)b*LL + r1)*256 + h*32 + tg*2;
    #pragma unroll
    for (int nt = 0; nt < 4; ++nt) {
        *(uint32_t*)(o0 + nt*8) = bf2(o[nt][0]*rd0, o[nt][1]*rd0);
        *(uint32_t*)(o1 + nt*8) = bf2(o[nt][2]*rd1, o[nt][3]*rd1);
    }
}

// ---------------------------------------------------------------------------
extern "C" void kernel_launch(void* const* d_in, const int* in_sizes, int n_in,
                              void* d_out, int out_size)
{
    const float* x      = (const float*)d_in[0];
    const float* ctx    = (const float*)d_in[1];
    const float* ln_x_w = (const float*)d_in[2];
    const float* ln_x_b = (const float*)d_in[3];
    const float* ln_c_w = (const float*)d_in[4];
    const float* ln_c_b = (const float*)d_in[5];
    const float* Wq     = (const float*)d_in[6];
    const float* bq     = (const float*)d_in[7];
    const float* Wk     = (const float*)d_in[8];
    const float* bk     = (const float*)d_in[9];
    const float* Wv     = (const float*)d_in[10];
    const float* bv     = (const float*)d_in[11];
    const float* Wp     = (const float*)d_in[12];
    const float* bp     = (const float*)d_in[13];
    const float* rel    = (const float*)d_in[14];
    float* out = (float*)d_out;

    cudaFuncSetAttribute(hgemm<0>, cudaFuncAttributeMaxDynamicSharedMemorySize, HG_DYN);
    cudaFuncSetAttribute(hgemm<1>, cudaFuncAttributeMaxDynamicSharedMemorySize, HG_DYN);

    ln_fused<<<dim3(LL/32, BB, 2), 256>>>(x, ctx, ln_x_w, ln_x_b, ln_c_w, ln_c_b);
    prep_kernel<<<(HEADS*BR*BR + 255)/256, 256>>>(rel, Wq, Wk, Wv, Wp);

    hgemm<0><<<dim3(BB*LL/128, INNER/128, 3), 256, HG_DYN>>>(bq, bk, bv, nullptr, nullptr);

    attn_hmma<<<dim3(LL/128, BB*HEADS), 256>>>();

    hgemm<1><<<dim3(BB*LL/128, INNER/128), 256, HG_DYN>>>(bp, nullptr, nullptr, out, x);
}

// round 15
// speedup vs baseline: 6.3785x; 1.0827x over previous
#include <cuda_runtime.h>
#include <cuda_bf16.h>
#include <math.h>
#include <cstdint>

#define HEADS 8
#define HEAD_DIM 32
#define CH 256
#define INNER 256
#define LL 2304
#define BB 4
#define TABLE_W 127     // 2*MAX_RES-1
#define BR 95           // 2*48-1
#define EPS 1e-6f
#define LOG2E 1.4426950408889634f
#define SC 0.25503486f  // (1/sqrt(32)) * log2(e)  -- folded into Q

// ---------------- scratch (device globals: no allocation allowed) ----------
__device__ __align__(128) __nv_bfloat16 g_xnb[BB*LL*CH];        // LN(x)   [b,l,c]
__device__ __align__(128) __nv_bfloat16 g_cnb[BB*LL*CH];        // LN(ctx) [b,l,c]
__device__ __align__(128) __nv_bfloat16 g_ob [BB*LL*INNER];     // attn out [b,l,c]
__device__ float g_biasc[HEADS*BR*BR];                          // bias * log2e
__device__ __align__(128) __nv_bfloat16 g_qb[BB*HEADS*LL*32];   // Q (pre-scaled by SC)
__device__ __align__(128) __nv_bfloat16 g_kb[BB*HEADS*LL*32];
__device__ __align__(128) __nv_bfloat16 g_vt[BB*HEADS*32*LL];   // V^T [bh][d][l]
__device__ __align__(128) __nv_bfloat16 g_wq[CH*INNER];
__device__ __align__(128) __nv_bfloat16 g_wk[CH*INNER];
__device__ __align__(128) __nv_bfloat16 g_wv[CH*INNER];
__device__ __align__(128) __nv_bfloat16 g_wp[CH*INNER];

// ---------------- small helpers --------------------------------------------
__device__ __forceinline__ float ex2f(float x) {
    float r;
    asm("ex2.approx.f32 %0, %1;" : "=f"(r) : "f"(x));
    return r;
}
__device__ __forceinline__ uint32_t bf2(float x, float y) {
    __nv_bfloat162 t = __float22bfloat162_rn(make_float2(x, y));
    return *(uint32_t*)&t;
}
__device__ __forceinline__ void mma16816(float* c, const uint32_t* a, const uint32_t* b) {
    asm volatile(
        "mma.sync.aligned.m16n8k16.row.col.f32.bf16.bf16.f32 "
        "{%0,%1,%2,%3}, {%4,%5,%6,%7}, {%8,%9}, {%0,%1,%2,%3};"
        : "+f"(c[0]), "+f"(c[1]), "+f"(c[2]), "+f"(c[3])
        : "r"(a[0]), "r"(a[1]), "r"(a[2]), "r"(a[3]), "r"(b[0]), "r"(b[1]));
}
__device__ __forceinline__ void ldsm4(uint32_t* r, uint32_t addr) {
    asm volatile("ldmatrix.sync.aligned.m8n8.x4.shared.b16 {%0,%1,%2,%3}, [%4];"
        : "=r"(r[0]), "=r"(r[1]), "=r"(r[2]), "=r"(r[3]) : "r"(addr));
}
__device__ __forceinline__ uint32_t smem_u32(const void* p) {
    uint32_t a;
    asm("{ .reg .u64 t; cvta.to.shared.u64 t, %1; cvt.u32.u64 %0, t; }" : "=r"(a) : "l"(p));
    return a;
}
__device__ __forceinline__ void cpa16(uint32_t dst, const void* src) {
    asm volatile("cp.async.cg.shared.global [%0], [%1], 16;"
        :: "r"(dst), "l"(__cvta_generic_to_global(src)) : "memory");
}
#define CP_COMMIT() asm volatile("cp.async.commit_group;" ::: "memory")
#define CP_WAIT(n)  asm volatile("cp.async.wait_group %0;" :: "n"(n) : "memory")

// ---------------- LayerNorm over C of NCHW -> bf16 [B, L, C] (fused x/ctx) -
__global__ void ln_fused(const float* __restrict__ x, const float* __restrict__ ctx,
                         const float* __restrict__ wx, const float* __restrict__ bx,
                         const float* __restrict__ wc, const float* __restrict__ bc)
{
    __shared__ float s[CH*33];
    __shared__ float rsum[8][32];
    __shared__ float rsq[8][32];
    __shared__ float mu_s[32];
    __shared__ float rs_s[32];

    const float* in = blockIdx.z ? ctx : x;
    const float* w  = blockIdx.z ? wc : wx;
    const float* bvec = blockIdx.z ? bc : bx;
    __nv_bfloat16* out = blockIdx.z ? g_cnb : g_xnb;

    int tx = threadIdx.x & 31;
    int ty = threadIdx.x >> 5;
    int b  = blockIdx.y;
    int l0 = blockIdx.x * 32;

    const float* inb = in + (size_t)b*CH*LL + l0;
    float sm = 0.f, sq = 0.f;
    #pragma unroll 4
    for (int cg = 0; cg < 32; ++cg) {
        int c = cg*8 + ty;
        float vv = inb[(size_t)c*LL + tx];
        s[c*33 + tx] = vv;
        sm += vv; sq += vv*vv;
    }
    rsum[ty][tx] = sm; rsq[ty][tx] = sq;
    __syncthreads();
    if (threadIdx.x < 32) {
        float a = 0.f, c2 = 0.f;
        #pragma unroll
        for (int j = 0; j < 8; ++j) { a += rsum[j][threadIdx.x]; c2 += rsq[j][threadIdx.x]; }
        float mu  = a * (1.f/CH);
        float var = c2 * (1.f/CH) - mu*mu;
        mu_s[threadIdx.x] = mu;
        rs_s[threadIdx.x] = rsqrtf(var + EPS);
    }
    __syncthreads();
    __nv_bfloat16* ob = out + ((size_t)b*LL + l0)*CH;
    #pragma unroll 4
    for (int i = threadIdx.x; i < 32*CH; i += 256) {
        int p = i >> 8, c = i & 255;
        float vv = s[c*33 + p];
        ob[(size_t)p*CH + c] =
            __float2bfloat16((vv - mu_s[p]) * rs_s[p] * w[c] + bvec[c]);
    }
}

// ---------------- prep: rel-bias compaction + fp32->bf16 weights -----------
// NOTE: grid must cover max(CH*INNER, HEADS*BR*BR) = 72200.
__global__ void prep_kernel(const float* __restrict__ rel_table,
                            const float* __restrict__ Wq, const float* __restrict__ Wk,
                            const float* __restrict__ Wv, const float* __restrict__ Wp)
{
    int i = blockIdx.x*256 + threadIdx.x;
    if (i < CH*INNER) {
        g_wq[i] = __float2bfloat16(Wq[i]);
        g_wk[i] = __float2bfloat16(Wk[i]);
        g_wv[i] = __float2bfloat16(Wv[i]);
        g_wp[i] = __float2bfloat16(Wp[i]);
    }
    if (i < HEADS*BR*BR) {
        int h  = i / (BR*BR);
        int rr = i - h*(BR*BR);
        int dh = rr / BR;
        int dw = rr - dh*BR;
        int idx = (dh + 16)*TABLE_W + (dw + 16);
        g_biasc[i] = rel_table[idx*HEADS + h] * LOG2E;
    }
}

// ---------------- HMMA GEMM, cp.async double-buffered ----------------------
// BM=128, BN=128, BK=64. PROJ=0: fused QKV (mode = blockIdx.z 0..2).
// PROJ=1: out-projection with residual (NCHW f32).
#define HG_BOFF 18432          // B tile offset within one buffer
#define HG_BUF  36864          // one double-buffer slot (A+B tiles)
#define HG_DYN  73728          // 2 buffers; transpose epilogue reuses [0, 67584)
template<int PROJ>
__global__ __launch_bounds__(256) void hgemm(const float* __restrict__ bias0,
                                             const float* __restrict__ bias1,
                                             const float* __restrict__ bias2,
                                             float* __restrict__ Cout,
                                             const float* __restrict__ resid)
{
    extern __shared__ char smc[];
    int mode = PROJ ? 3 : blockIdx.z;
    const __nv_bfloat16* A  = (mode == 0) ? g_xnb : (mode == 3) ? g_ob : g_cnb;
    const __nv_bfloat16* Wb = (mode == 0) ? g_wq : (mode == 1) ? g_wk
                            : (mode == 2) ? g_wv : g_wp;
    const float* bias = PROJ ? bias0
                      : (mode == 0 ? bias0 : (mode == 1 ? bias1 : bias2));

    int tid = threadIdx.x;
    int w = tid >> 5, lane = tid & 31;
    int g = lane >> 2, tg = lane & 3;
    int m0 = blockIdx.x * 128, n0 = blockIdx.y * 128;

    // cp.async staging roles: thread -> (row, 64B half), 4x16B each of A and B
    int srow = tid >> 1, shalf = tid & 1;
    const __nv_bfloat16* agp = A  + (size_t)(m0 + srow)*256 + shalf*32;
    const __nv_bfloat16* bgp = Wb + (size_t)(n0 + srow)*256 + shalf*32;
    uint32_t sb = smem_u32(smc);
    uint32_t aDst = sb + (uint32_t)(srow*144 + shalf*64);
    uint32_t bDst = aDst + HG_BOFF;

    // ldmatrix lane bases
    int tA = lane >> 3, rA = lane & 7;
    uint32_t aBase = sb + (uint32_t)((w*16 + (tA & 1)*8 + rA)*144 + (tA >> 1)*16);
    uint32_t bBase = sb + HG_BOFF + (uint32_t)(((tA >> 1)*8 + rA)*144 + (tA & 1)*16);

    float c[16][4];
    #pragma unroll
    for (int i = 0; i < 16; ++i) { c[i][0]=c[i][1]=c[i][2]=c[i][3]=0.f; }

    // preload chunk 0 into buffer 0
    #pragma unroll
    for (int j = 0; j < 4; ++j) {
        cpa16(aDst + j*16, agp + j*8);
        cpa16(bDst + j*16, bgp + j*8);
    }
    CP_COMMIT();

    #pragma unroll
    for (int kc = 0; kc < 4; ++kc) {
        __syncthreads();                       // all prior compute done
        if (kc < 3) {
            uint32_t nb = (uint32_t)(((kc + 1) & 1) * HG_BUF);
            #pragma unroll
            for (int j = 0; j < 4; ++j) {
                cpa16(aDst + nb + j*16, agp + (kc+1)*64 + j*8);
                cpa16(bDst + nb + j*16, bgp + (kc+1)*64 + j*8);
            }
            CP_COMMIT();
            CP_WAIT(1);
        } else {
            CP_WAIT(0);
        }
        __syncthreads();                       // staged chunk kc visible

        uint32_t bo = (uint32_t)((kc & 1) * HG_BUF);
        #pragma unroll
        for (int ks = 0; ks < 4; ++ks) {
            uint32_t a[4];
            ldsm4(a, aBase + bo + ks*32);
            #pragma unroll
            for (int p = 0; p < 8; ++p) {
                uint32_t bb[4];
                ldsm4(bb, bBase + bo + p*2304 + ks*32);
                mma16816(c[2*p],     a, bb);
                mma16816(c[2*p + 1], a, bb + 2);
            }
        }
    }

    int b  = m0 / LL;                 // 128-row tiles never straddle batches
    int l0 = m0 - b*LL;
    int r0 = l0 + w*16 + g, r1 = r0 + 8;

    if (!PROJ && mode <= 1) {
        __nv_bfloat16* dst = (mode == 0) ? g_qb : g_kb;
        const float scl = (mode == 0) ? SC : 1.0f;
        #pragma unroll
        for (int nt = 0; nt < 16; ++nt) {
            int n = n0 + nt*8 + tg*2;
            float2 bb = *(const float2*)(bias + n);
            int hh = n >> 5, d0 = n & 31;
            uint32_t u0 = bf2((c[nt][0]+bb.x)*scl, (c[nt][1]+bb.y)*scl);
            uint32_t u1 = bf2((c[nt][2]+bb.x)*scl, (c[nt][3]+bb.y)*scl);
            *(uint32_t*)(&dst[((size_t)(b*8 + hh)*LL + r0)*32 + d0]) = u0;
            *(uint32_t*)(&dst[((size_t)(b*8 + hh)*LL + r1)*32 + d0]) = u1;
        }
    } else {
        // transpose through smem (reuse staging buffers)
        __syncthreads();
        float* tr = (float*)smc;
        int lr0 = w*16 + g, lr1 = lr0 + 8;
        #pragma unroll
        for (int nt = 0; nt < 16; ++nt) {
            int nl = nt*8 + tg*2;
            tr[nl*132 + lr0]       = c[nt][0];
            tr[(nl + 1)*132 + lr0] = c[nt][1];
            tr[nl*132 + lr1]       = c[nt][2];
            tr[(nl + 1)*132 + lr1] = c[nt][3];
        }
        __syncthreads();
        int n = tid >> 1, lh = (tid & 1)*64;
        int gn = n0 + n;
        float bj = bias[gn];
        const float* trp = tr + n*132 + lh;
        if (PROJ) {
            size_t ad = ((size_t)b*256 + gn)*LL + l0 + lh;
            #pragma unroll
            for (int j = 0; j < 16; ++j) {
                float4 xv = ((const float4*)(resid + ad))[j];
                float4 tv = *(const float4*)(trp + j*4);
                ((float4*)(Cout + ad))[j] = make_float4(
                    xv.x + tv.x + bj, xv.y + tv.y + bj,
                    xv.z + tv.z + bj, xv.w + tv.w + bj);
            }
        } else {  // mode 2 -> g_vt bf16 [bh][d][l]
            int hh = gn >> 5, d = gn & 31;
            __nv_bfloat16* vd = g_vt + ((size_t)(b*8 + hh)*32 + d)*LL + l0 + lh;
            #pragma unroll
            for (int j = 0; j < 8; ++j) {
                float4 t0 = *(const float4*)(trp + j*8);
                float4 t1 = *(const float4*)(trp + j*8 + 4);
                uint4 u;
                u.x = bf2(t0.x + bj, t0.y + bj);
                u.y = bf2(t0.z + bj, t0.w + bj);
                u.z = bf2(t1.x + bj, t1.y + bj);
                u.w = bf2(t1.z + bj, t1.w + bj);
                *(uint4*)(vd + j*8) = u;
            }
        }
    }
}

// ---------------- HMMA flash attention (ldmatrix + cp.async) ---------------
// grid (LL/128, BB*HEADS), 256 threads (8 warps). Warp w owns q-rows
// [l0 + w*16, +16). Keys in 64-chunks, double-buffered.
// Dynamic smem layout (bytes):
#define AT_K   0        // K tiles: 2 x 64*80   = 10240
#define AT_V   10240    // V tiles: 2 x 32*144  =  9216
#define AT_KO  19456    // kOffE[LL/2] int     =  4608 (kOff of EVEN keys only)
#define AT_BP  24064    // biasP[4848] float2  = 38784 ({bias[j], bias[j-1]})
#define AT_TOT 62848
__global__ void __launch_bounds__(256) attn_hmma()
{
    extern __shared__ char sma[];

    int tid = threadIdx.x;
    int w = tid >> 5, lane = tid & 31;
    int g = lane >> 2, tg = lane & 3;
    int bh = blockIdx.y;
    int b = bh >> 3, h = bh & 7;
    int l0 = blockIdx.x * 128;

    int* kOffE = (int*)(sma + AT_KO);
    float2* biasP = (float2*)(sma + AT_BP);

    // kOff for even keys: key = 2j never has kw == 47 (48 even), so the pair
    // (2j, 2j+1) never crosses a w-row: bias idx of 2j+1 = bias idx of 2j - 1.
    for (int j = tid; j < LL/2; j += 256) {
        int key = 2*j;
        int kh = key / 48;
        kOffE[j] = kh*BR + (key - kh*48);
    }
    // paired bias sub-table for this q-tile's qh range
    int qh_min = l0 / 48;
    {
        int qh_max = (l0 + 127) / 48;
        int rows = qh_max - qh_min + 48;          // <= 51
        const float* bc = g_biasc + h*BR*BR + qh_min*BR;
        for (int i = tid; i < rows*BR; i += 256) {
            float hi = bc[i];
            float lo = (i > 0) ? bc[i-1] : 0.f;
            biasP[i] = make_float2(hi, lo);
        }
    }

    int r0 = l0 + w*16 + g;
    int r1 = r0 + 8;
    uint32_t qa[2][4];
    {
        const __nv_bfloat16* q0 = g_qb + ((size_t)bh*LL + r0)*32;
        const __nv_bfloat16* q1 = q0 + 8*32;
        #pragma unroll
        for (int ks = 0; ks < 2; ++ks) {
            qa[ks][0] = *(const uint32_t*)(q0 + ks*16 + tg*2);
            qa[ks][1] = *(const uint32_t*)(q1 + ks*16 + tg*2);
            qa[ks][2] = *(const uint32_t*)(q0 + ks*16 + tg*2 + 8);
            qa[ks][3] = *(const uint32_t*)(q1 + ks*16 + tg*2 + 8);
        }
    }
    int qh0 = r0 / 48, qw0 = r0 - qh0*48;
    int qh1 = r1 / 48, qw1 = r1 - qh1*48;
    int qb0 = (qh0 - qh_min + 47)*BR + qw0 + 47;
    int qb1 = (qh1 - qh_min + 47)*BR + qw1 + 47;

    float o[4][4];
    #pragma unroll
    for (int i = 0; i < 4; ++i) { o[i][0]=o[i][1]=o[i][2]=o[i][3]=0.f; }
    float ls0 = 0.f, ls1 = 0.f;

    const __nv_bfloat16* kg = g_kb + (size_t)bh*LL*32;
    const __nv_bfloat16* vg = g_vt + (size_t)bh*32*LL;

    // cp.async roles: 1 x 16B per thread for K and V each
    int kkey = tid >> 2, kseg = tid & 3;
    int vd   = tid >> 3, vseg = tid & 7;
    uint32_t kDst = smem_u32(sma + AT_K) + (uint32_t)(kkey*80 + kseg*16);
    uint32_t vDst = smem_u32(sma + AT_V) + (uint32_t)(vd*144 + vseg*16);

    // ldmatrix lane bases: lane = t*8 + r -> tile t, row r
    int t4 = lane >> 3, r8 = lane & 7;
    uint32_t kAdr0 = smem_u32(sma + AT_K) + (uint32_t)((8*(t4 >> 1) + r8)*80  + (t4 & 1)*16);
    uint32_t vAdr0 = smem_u32(sma + AT_V) + (uint32_t)((8*(t4 >> 1) + r8)*144 + (t4 & 1)*16);

    // preload chunk 0
    cpa16(kDst, kg + (size_t)kkey*32 + kseg*8);
    cpa16(vDst, vg + (size_t)vd*LL + vseg*8);
    CP_COMMIT();

    for (int kt = 0; kt < LL/64; ++kt) {
        int cur = kt & 1;
        __syncthreads();                       // prev compute done everywhere
        if (kt < LL/64 - 1) {
            uint32_t nxt = (uint32_t)(cur ^ 1);
            cpa16(kDst + nxt*5120, kg + (size_t)((kt+1)*64 + kkey)*32 + kseg*8);
            cpa16(vDst + nxt*4608, vg + (size_t)vd*LL + (kt+1)*64 + vseg*8);
            CP_COMMIT();
            CP_WAIT(1);
        } else {
            CP_WAIT(0);
        }
        __syncthreads();                       // chunk kt visible to all

        uint32_t kAdr = kAdr0 + (uint32_t)(cur*5120);
        uint32_t vAdr = vAdr0 + (uint32_t)(cur*4608);

        // ---- S = Q K^T : 8 ldsm.x4 + 16 HMMA
        float S[8][4];
        #pragma unroll
        for (int ntp = 0; ntp < 4; ++ntp) {
            S[2*ntp][0]=S[2*ntp][1]=S[2*ntp][2]=S[2*ntp][3]=0.f;
            S[2*ntp+1][0]=S[2*ntp+1][1]=S[2*ntp+1][2]=S[2*ntp+1][3]=0.f;
            #pragma unroll
            for (int ks = 0; ks < 2; ++ks) {
                uint32_t bb[4];
                ldsm4(bb, kAdr + ntp*1280 + ks*32);
                mma16816(S[2*ntp],     qa[ks], bb);
                mma16816(S[2*ntp + 1], qa[ks], bb + 2);
            }
        }

        // ---- softmax (base-2, no max-sub) + pack P fragments
        // paired bias: one LDS.64 per (q-row, key-pair)
        uint32_t pa[4][4];
        int koIdx = kt*32 + tg;                // index into kOffE (even keys)
        #pragma unroll
        for (int nt = 0; nt < 8; ++nt) {
            int ko = kOffE[koIdx + nt*4];
            float2 bp0 = biasP[qb0 - ko];      // {bias[j], bias[j-1]}
            float2 bp1 = biasP[qb1 - ko];
            float p0 = ex2f(S[nt][0] + bp0.x);
            float p1 = ex2f(S[nt][1] + bp0.y);
            float p2 = ex2f(S[nt][2] + bp1.x);
            float p3 = ex2f(S[nt][3] + bp1.y);
            ls0 += p0 + p1;
            ls1 += p2 + p3;
            pa[nt >> 1][(nt & 1)*2 + 0] = bf2(p0, p1);
            pa[nt >> 1][(nt & 1)*2 + 1] = bf2(p2, p3);
        }

        // ---- O += P V : 8 ldsm.x4 + 16 HMMA
        #pragma unroll
        for (int ntp = 0; ntp < 2; ++ntp) {
            #pragma unroll
            for (int ks = 0; ks < 4; ++ks) {
                uint32_t bb[4];
                ldsm4(bb, vAdr + ntp*2304 + ks*32);
                mma16816(o[2*ntp],     pa[ks], bb);
                mma16816(o[2*ntp + 1], pa[ks], bb + 2);
            }
        }
    }

    ls0 += __shfl_xor_sync(0xFFFFFFFFu, ls0, 1);
    ls0 += __shfl_xor_sync(0xFFFFFFFFu, ls0, 2);
    ls1 += __shfl_xor_sync(0xFFFFFFFFu, ls1, 1);
    ls1 += __shfl_xor_sync(0xFFFFFFFFu, ls1, 2);
    float rd0 = 1.f / ls0, rd1 = 1.f / ls1;

    __nv_bfloat16* o0 = g_ob + ((size_t)b*LL + r0)*256 + h*32 + tg*2;
    __nv_bfloat16* o1 = g_ob + ((size_t)b*LL + r1)*256 + h*32 + tg*2;
    #pragma unroll
    for (int nt = 0; nt < 4; ++nt) {
        *(uint32_t*)(o0 + nt*8) = bf2(o[nt][0]*rd0, o[nt][1]*rd0);
        *(uint32_t*)(o1 + nt*8) = bf2(o[nt][2]*rd1, o[nt][3]*rd1);
    }
}

// ---------------------------------------------------------------------------
extern "C" void kernel_launch(void* const* d_in, const int* in_sizes, int n_in,
                              void* d_out, int out_size)
{
    const float* x      = (const float*)d_in[0];
    const float* ctx    = (const float*)d_in[1];
    const float* ln_x_w = (const float*)d_in[2];
    const float* ln_x_b = (const float*)d_in[3];
    const float* ln_c_w = (const float*)d_in[4];
    const float* ln_c_b = (const float*)d_in[5];
    const float* Wq     = (const float*)d_in[6];
    const float* bq     = (const float*)d_in[7];
    const float* Wk     = (const float*)d_in[8];
    const float* bk     = (const float*)d_in[9];
    const float* Wv     = (const float*)d_in[10];
    const float* bv     = (const float*)d_in[11];
    const float* Wp     = (const float*)d_in[12];
    const float* bp     = (const float*)d_in[13];
    const float* rel    = (const float*)d_in[14];
    float* out = (float*)d_out;

    cudaFuncSetAttribute(hgemm<0>, cudaFuncAttributeMaxDynamicSharedMemorySize, HG_DYN);
    cudaFuncSetAttribute(hgemm<1>, cudaFuncAttributeMaxDynamicSharedMemorySize, HG_DYN);
    cudaFuncSetAttribute(attn_hmma, cudaFuncAttributeMaxDynamicSharedMemorySize, AT_TOT);

    ln_fused<<<dim3(LL/32, BB, 2), 256>>>(x, ctx, ln_x_w, ln_x_b, ln_c_w, ln_c_b);
    prep_kernel<<<(HEADS*BR*BR + 255)/256, 256>>>(rel, Wq, Wk, Wv, Wp);

    hgemm<0><<<dim3(BB*LL/128, INNER/128, 3), 256, HG_DYN>>>(bq, bk, bv, nullptr, nullptr);

    attn_hmma<<<dim3(LL/128, BB*HEADS), 256, AT_TOT>>>();

    hgemm<1><<<dim3(BB*LL/128, INNER/128), 256, HG_DYN>>>(bp, nullptr, nullptr, out, x);
}